// round 1
// baseline (speedup 1.0000x reference)
#include <cuda_runtime.h>

// Problem constants
#define BSZ   2
#define SEQ   2048
#define HIDN  1024
#define HEADS 16
#define HD    64
#define NQB   32            // SEQ / 64
#define MROWS (BSZ*SEQ)     // 4096

// Scratch (device globals: no allocation allowed in kernel_launch)
__device__ float g_q[BSZ*HEADS*SEQ*HD];     // [B,H,S,D]
__device__ float g_k[BSZ*HEADS*SEQ*HD];
__device__ float g_v[BSZ*HEADS*SEQ*HD];
__device__ float g_attn[BSZ*SEQ*HIDN];      // [B,S,HID]

// ---------------------------------------------------------------------------
// GEMM: C[M,N] = A[M,K] @ W[N,K]^T + bias[N]
// A row-major [M,K]; W row-major [N,K] (torch Linear weight layout).
// scatter==0: C row-major [M,N]
// scatter==1: C is [B,HEADS,SEQ,HD]  (m -> (b,s), n -> (h,d))
// BM=BN=128, BK=8, 256 threads, 8x8 per-thread microtile.
// ---------------------------------------------------------------------------
__global__ __launch_bounds__(256) void gemm_nt_kernel(
    const float* __restrict__ A, const float* __restrict__ W,
    const float* __restrict__ bias, float* __restrict__ C,
    int M, int N, int K, int scatter)
{
    __shared__ float As[8][128];
    __shared__ float Bs[8][128];

    const int tid = threadIdx.x;
    const int tr  = tid >> 4;        // 0..15
    const int tc  = tid & 15;        // 0..15
    const int lr  = tid >> 1;        // 0..127  (load row)
    const int lc  = (tid & 1) << 2;  // 0 or 4  (load col group)

    const float* Ab = A + (size_t)blockIdx.y * 128 * K;
    const float* Wb = W + (size_t)blockIdx.x * 128 * K;

    float acc[8][8];
#pragma unroll
    for (int i = 0; i < 8; i++)
#pragma unroll
        for (int j = 0; j < 8; j++) acc[i][j] = 0.f;

    for (int kt = 0; kt < K; kt += 8) {
        float4 a4 = *(const float4*)(Ab + (size_t)lr * K + kt + lc);
        float4 b4 = *(const float4*)(Wb + (size_t)lr * K + kt + lc);
        As[lc + 0][lr] = a4.x; As[lc + 1][lr] = a4.y;
        As[lc + 2][lr] = a4.z; As[lc + 3][lr] = a4.w;
        Bs[lc + 0][lr] = b4.x; Bs[lc + 1][lr] = b4.y;
        Bs[lc + 2][lr] = b4.z; Bs[lc + 3][lr] = b4.w;
        __syncthreads();

#pragma unroll
        for (int k = 0; k < 8; k++) {
            float ar[8], br[8];
#pragma unroll
            for (int i = 0; i < 8; i++) ar[i] = As[k][tr * 8 + i];
#pragma unroll
            for (int j = 0; j < 8; j++) br[j] = Bs[k][tc * 8 + j];
#pragma unroll
            for (int i = 0; i < 8; i++)
#pragma unroll
                for (int j = 0; j < 8; j++)
                    acc[i][j] += ar[i] * br[j];
        }
        __syncthreads();
    }

#pragma unroll
    for (int i = 0; i < 8; i++) {
        const int m = blockIdx.y * 128 + tr * 8 + i;
#pragma unroll
        for (int j = 0; j < 8; j++) {
            const int n = blockIdx.x * 128 + tc * 8 + j;
            const float v = acc[i][j] + bias[n];
            if (!scatter) {
                C[(size_t)m * N + n] = v;
            } else {
                const int b = m >> 11, s = m & 2047;   // SEQ = 2048
                const int h = n >> 6,  d = n & 63;     // HD  = 64
                C[(((size_t)(b * HEADS + h)) * SEQ + s) * HD + d] = v;
            }
        }
    }
}

// ---------------------------------------------------------------------------
// Block-causal flash attention. One CTA per (q-block of 64, head, batch).
// Mask is block-granular (BLOCK=64) => a 64x64 tile is either fully visible
// (kb <= qb) or fully masked -> no elementwise masking needed.
// 256 threads, thread grid 16x16, each owns a 4x4 microtile of the 64x64
// score/P tile and a 4x4 slice of the 64x64 output accumulator.
// ---------------------------------------------------------------------------
#define ATTN_SMEM_FLOATS (64*64 + 64*65 + 64*65)
#define ATTN_SMEM_BYTES  (ATTN_SMEM_FLOATS * 4)

__global__ __launch_bounds__(256) void attn_kernel(
    const float* __restrict__ Q, const float* __restrict__ K,
    const float* __restrict__ V, float* __restrict__ O)
{
    extern __shared__ float smem[];
    float* Qs = smem;                 // [64][64]   stride 64
    float* Ks = smem + 64 * 64;       // [64][65]   stride 65 (K tile, reused for V)
    float* Ps = Ks + 64 * 65;         // [64][65]   stride 65

    const int qb = blockIdx.x;
    const int h  = blockIdx.y;
    const int b  = blockIdx.z;
    const int tid = threadIdx.x;
    const int ty = tid >> 4;          // 0..15 -> q rows ty*4..ty*4+3
    const int tx = tid & 15;          // 0..15 -> cols tx*4..tx*4+3

    const size_t hb = ((size_t)(b * HEADS + h)) * SEQ * HD;
    const float scale = 0.125f;       // 1/sqrt(64)

    // Load Q tile (pre-scaled)
    {
        const float* Qg = Q + hb + (size_t)qb * 64 * HD;
        for (int p = tid; p < 1024; p += 256) {
            const int r = p >> 4, c = (p & 15) << 2;
            float4 v = *(const float4*)(Qg + r * HD + c);
            float* dst = Qs + r * 64 + c;
            dst[0] = v.x * scale; dst[1] = v.y * scale;
            dst[2] = v.z * scale; dst[3] = v.w * scale;
        }
    }

    float m_i[4], l_i[4], o[4][4];
#pragma unroll
    for (int i = 0; i < 4; i++) {
        m_i[i] = -1e30f; l_i[i] = 0.f;
#pragma unroll
        for (int c = 0; c < 4; c++) o[i][c] = 0.f;
    }

    for (int kb = 0; kb <= qb; kb++) {
        __syncthreads();   // prior V reads (and Q store on iter 0) complete
        // Load K tile
        {
            const float* Kg = K + hb + (size_t)kb * 64 * HD;
            for (int p = tid; p < 1024; p += 256) {
                const int r = p >> 4, c = (p & 15) << 2;
                float4 v = *(const float4*)(Kg + r * HD + c);
                float* dst = Ks + r * 65 + c;
                dst[0] = v.x; dst[1] = v.y; dst[2] = v.z; dst[3] = v.w;
            }
        }
        __syncthreads();

        // S = (Q*scale) K^T   (4x4 per thread)
        float sacc[4][4];
#pragma unroll
        for (int i = 0; i < 4; i++)
#pragma unroll
            for (int j = 0; j < 4; j++) sacc[i][j] = 0.f;

#pragma unroll 4
        for (int dd = 0; dd < 64; dd++) {
            float qv[4], kv[4];
#pragma unroll
            for (int i = 0; i < 4; i++) qv[i] = Qs[(ty * 4 + i) * 64 + dd];
#pragma unroll
            for (int j = 0; j < 4; j++) kv[j] = Ks[(tx * 4 + j) * 65 + dd];
#pragma unroll
            for (int i = 0; i < 4; i++)
#pragma unroll
                for (int j = 0; j < 4; j++)
                    sacc[i][j] += qv[i] * kv[j];
        }

        // Online softmax (reduce over the 16 tx lanes; same half-warp)
#pragma unroll
        for (int i = 0; i < 4; i++) {
            float mt = fmaxf(fmaxf(sacc[i][0], sacc[i][1]),
                             fmaxf(sacc[i][2], sacc[i][3]));
#pragma unroll
            for (int off = 8; off >= 1; off >>= 1)
                mt = fmaxf(mt, __shfl_xor_sync(0xffffffffu, mt, off));
            const float mnew = fmaxf(m_i[i], mt);
            const float corr = __expf(m_i[i] - mnew);
            float ls = 0.f;
#pragma unroll
            for (int j = 0; j < 4; j++) {
                const float pv = __expf(sacc[i][j] - mnew);
                sacc[i][j] = pv;
                ls += pv;
            }
#pragma unroll
            for (int off = 8; off >= 1; off >>= 1)
                ls += __shfl_xor_sync(0xffffffffu, ls, off);
            l_i[i] = l_i[i] * corr + ls;
            m_i[i] = mnew;
#pragma unroll
            for (int c = 0; c < 4; c++) o[i][c] *= corr;
#pragma unroll
            for (int j = 0; j < 4; j++)
                Ps[(ty * 4 + i) * 65 + tx * 4 + j] = sacc[i][j];
        }
        __syncthreads();   // Ps visible; K reads complete before V overwrite

        // Load V tile into Ks
        {
            const float* Vg = V + hb + (size_t)kb * 64 * HD;
            for (int p = tid; p < 1024; p += 256) {
                const int r = p >> 4, c = (p & 15) << 2;
                float4 v = *(const float4*)(Vg + r * HD + c);
                float* dst = Ks + r * 65 + c;
                dst[0] = v.x; dst[1] = v.y; dst[2] = v.z; dst[3] = v.w;
            }
        }
        __syncthreads();

        // O += P @ V
#pragma unroll 4
        for (int j = 0; j < 64; j++) {
            float pv[4], vv[4];
#pragma unroll
            for (int i = 0; i < 4; i++) pv[i] = Ps[(ty * 4 + i) * 65 + j];
#pragma unroll
            for (int c = 0; c < 4; c++) vv[c] = Ks[j * 65 + tx * 4 + c];
#pragma unroll
            for (int i = 0; i < 4; i++)
#pragma unroll
                for (int c = 0; c < 4; c++)
                    o[i][c] += pv[i] * vv[c];
        }
    }

    // Finalize: divide by l, write [B,S,HID]
#pragma unroll
    for (int i = 0; i < 4; i++) {
        const float inv = 1.f / l_i[i];
        const int srow = b * SEQ + qb * 64 + ty * 4 + i;
#pragma unroll
        for (int c = 0; c < 4; c++) {
            O[(size_t)srow * HIDN + h * HD + tx * 4 + c] = o[i][c] * inv;
        }
    }
}

// ---------------------------------------------------------------------------
extern "C" void kernel_launch(void* const* d_in, const int* in_sizes, int n_in,
                              void* d_out, int out_size)
{
    const float* x  = (const float*)d_in[0];
    const float* Wq = (const float*)d_in[1];
    const float* bq = (const float*)d_in[2];
    const float* Wk = (const float*)d_in[3];
    const float* bk = (const float*)d_in[4];
    const float* Wv = (const float*)d_in[5];
    const float* bv = (const float*)d_in[6];
    const float* Wo = (const float*)d_in[7];
    const float* bo = (const float*)d_in[8];
    float* out = (float*)d_out;

    float *q, *k, *v, *attn;
    cudaGetSymbolAddress((void**)&q,    g_q);
    cudaGetSymbolAddress((void**)&k,    g_k);
    cudaGetSymbolAddress((void**)&v,    g_v);
    cudaGetSymbolAddress((void**)&attn, g_attn);

    cudaFuncSetAttribute(attn_kernel,
                         cudaFuncAttributeMaxDynamicSharedMemorySize,
                         ATTN_SMEM_BYTES);

    dim3 ggrid(HIDN / 128, MROWS / 128);   // (8, 32)

    gemm_nt_kernel<<<ggrid, 256>>>(x, Wq, bq, q, MROWS, HIDN, HIDN, 1);
    gemm_nt_kernel<<<ggrid, 256>>>(x, Wk, bk, k, MROWS, HIDN, HIDN, 1);
    gemm_nt_kernel<<<ggrid, 256>>>(x, Wv, bv, v, MROWS, HIDN, HIDN, 1);

    attn_kernel<<<dim3(NQB, HEADS, BSZ), 256, ATTN_SMEM_BYTES>>>(q, k, v, attn);

    gemm_nt_kernel<<<ggrid, 256>>>(attn, Wo, bo, out, MROWS, HIDN, HIDN, 0);
}

// round 5
// speedup vs baseline: 1.4364x; 1.4364x over previous
#include <cuda_runtime.h>
#include <cuda_bf16.h>

// Problem constants
#define BSZ   2
#define SEQ   2048
#define HIDN  1024
#define HEADS 16
#define HD    64
#define NQB   32            // SEQ / 64
#define MROWS (BSZ*SEQ)     // 4096

// Scratch (device globals: no allocation allowed in kernel_launch)
__device__ float g_q[BSZ*HEADS*SEQ*HD];     // [B,H,S,D]
__device__ float g_k[BSZ*HEADS*SEQ*HD];
__device__ float g_v[BSZ*HEADS*SEQ*HD];
__device__ float g_attn[BSZ*SEQ*HIDN];      // [B,S,HID]

// ===========================================================================
// mma.sync helpers (base-PTX, works on target sm_103)
// ===========================================================================
__device__ __forceinline__ unsigned smem_u32(const void* p) {
    unsigned a;
    asm("{ .reg .u64 t; cvta.to.shared.u64 t, %1; cvt.u32.u64 %0, t; }"
        : "=r"(a) : "l"(p));
    return a;
}

__device__ __forceinline__ void ldsm4(unsigned* r, unsigned addr) {
    asm volatile("ldmatrix.sync.aligned.m8n8.x4.shared.b16 {%0,%1,%2,%3}, [%4];"
                 : "=r"(r[0]), "=r"(r[1]), "=r"(r[2]), "=r"(r[3]) : "r"(addr));
}

__device__ __forceinline__ void mma16816(float* c, const unsigned* a,
                                         const unsigned* b) {
    asm volatile(
        "mma.sync.aligned.m16n8k16.row.col.f32.bf16.bf16.f32 "
        "{%0,%1,%2,%3}, {%4,%5,%6,%7}, {%8,%9}, {%0,%1,%2,%3};"
        : "+f"(c[0]), "+f"(c[1]), "+f"(c[2]), "+f"(c[3])
        : "r"(a[0]), "r"(a[1]), "r"(a[2]), "r"(a[3]), "r"(b[0]), "r"(b[1]));
}

__device__ __forceinline__ unsigned pack_bf16(__nv_bfloat16 x, __nv_bfloat16 y) {
    return ((unsigned)__bfloat16_as_ushort(y) << 16) | __bfloat16_as_ushort(x);
}

// ===========================================================================
// GEMM: C[M,N] = A[M,K] @ W[N,K]^T + bias[N]  via bf16 3-split on mma.sync.
// BM=BN=128, BK=32, 256 threads (8 warps, 2x4), warp tile 64x32.
// scatter==1: C written as [B,HEADS,SEQ,HD].
// SMEM: A_hi/A_lo/W_hi/W_lo, each [128][40] bf16 (stride 40 elems = 80B).
// ===========================================================================
#define GS_STRIDE 40
#define GS_TILE   (128 * GS_STRIDE)            // elems per tile (5120)
#define GSM_BYTES (4 * GS_TILE * 2)            // 40960 B

__global__ __launch_bounds__(256, 1)
void gemm_mma_kernel(const float* __restrict__ A, const float* __restrict__ W,
                     const float* __restrict__ bias, float* __restrict__ C,
                     int scatter)
{
    extern __shared__ char gsm[];
    __nv_bfloat16* a_hi = (__nv_bfloat16*)gsm;
    __nv_bfloat16* a_lo = a_hi + GS_TILE;
    __nv_bfloat16* w_hi = a_lo + GS_TILE;
    __nv_bfloat16* w_lo = w_hi + GS_TILE;

    const int tid  = threadIdx.x;
    const int lane = tid & 31;
    const int wid  = tid >> 5;
    const int wm   = wid >> 2;                 // 0..1
    const int wn   = wid & 3;                  // 0..3
    const int bn = blockIdx.x, bm = blockIdx.y;

    const float* Ag = A + (size_t)bm * 128 * HIDN;
    const float* Wg = W + (size_t)bn * 128 * HIDN;

    // Per-thread staging: 4 float4 of A + 4 of W per chunk
    const int lr  = tid >> 3;                  // 0..31 base row (x4 via +32)
    const int lc4 = (tid & 7) << 2;            // 0..28

    float4 va[4], vb[4];

    auto load_chunk = [&](int kt) {
#pragma unroll
        for (int i = 0; i < 4; i++) {
            const int r = lr + i * 32;
            va[i] = *(const float4*)(Ag + (size_t)r * HIDN + kt + lc4);
            vb[i] = *(const float4*)(Wg + (size_t)r * HIDN + kt + lc4);
        }
    };

    auto store_chunk = [&]() {
#pragma unroll
        for (int i = 0; i < 4; i++) {
            const int r = lr + i * 32;
            const int e = r * GS_STRIDE + lc4;
            float4 x = va[i];
            __nv_bfloat16 h0 = __float2bfloat16_rn(x.x);
            __nv_bfloat16 h1 = __float2bfloat16_rn(x.y);
            __nv_bfloat16 h2 = __float2bfloat16_rn(x.z);
            __nv_bfloat16 h3 = __float2bfloat16_rn(x.w);
            *(unsigned*)(a_hi + e)     = pack_bf16(h0, h1);
            *(unsigned*)(a_hi + e + 2) = pack_bf16(h2, h3);
            *(unsigned*)(a_lo + e)     = pack_bf16(
                __float2bfloat16_rn(x.x - __bfloat162float(h0)),
                __float2bfloat16_rn(x.y - __bfloat162float(h1)));
            *(unsigned*)(a_lo + e + 2) = pack_bf16(
                __float2bfloat16_rn(x.z - __bfloat162float(h2)),
                __float2bfloat16_rn(x.w - __bfloat162float(h3)));
            float4 y = vb[i];
            h0 = __float2bfloat16_rn(y.x);
            h1 = __float2bfloat16_rn(y.y);
            h2 = __float2bfloat16_rn(y.z);
            h3 = __float2bfloat16_rn(y.w);
            *(unsigned*)(w_hi + e)     = pack_bf16(h0, h1);
            *(unsigned*)(w_hi + e + 2) = pack_bf16(h2, h3);
            *(unsigned*)(w_lo + e)     = pack_bf16(
                __float2bfloat16_rn(y.x - __bfloat162float(h0)),
                __float2bfloat16_rn(y.y - __bfloat162float(h1)));
            *(unsigned*)(w_lo + e + 2) = pack_bf16(
                __float2bfloat16_rn(y.z - __bfloat162float(h2)),
                __float2bfloat16_rn(y.w - __bfloat162float(h3)));
        }
    };

    float acc[4][4][4];
#pragma unroll
    for (int i = 0; i < 4; i++)
#pragma unroll
        for (int j = 0; j < 4; j++)
#pragma unroll
            for (int k = 0; k < 4; k++) acc[i][j][k] = 0.f;

    // ldmatrix lane addressing (element offsets)
    const int fr = lane & 15;          // fragment row within 16
    const int fc = (lane >> 4) << 3;   // 0 or 8 (k offset)
    const unsigned sa_hi = smem_u32(a_hi);
    const unsigned sa_lo = smem_u32(a_lo);
    const unsigned sw_hi = smem_u32(w_hi);
    const unsigned sw_lo = smem_u32(w_lo);

    load_chunk(0);
    store_chunk();
    __syncthreads();

    for (int c = 0; c < HIDN / 32; c++) {
        if (c + 1 < HIDN / 32) load_chunk((c + 1) * 32);

#pragma unroll
        for (int ks = 0; ks < 2; ks++) {
            const int kcol = ks * 16 + fc;
            unsigned ah[4][4], al[4][4], bh[4][2], bl[4][2];
#pragma unroll
            for (int mt = 0; mt < 4; mt++) {
                const unsigned off =
                    ((wm * 64 + mt * 16 + fr) * GS_STRIDE + kcol) * 2;
                ldsm4(ah[mt], sa_hi + off);
                ldsm4(al[mt], sa_lo + off);
            }
#pragma unroll
            for (int ntp = 0; ntp < 2; ntp++) {
                const unsigned off =
                    ((wn * 32 + ntp * 16 + fr) * GS_STRIDE + kcol) * 2;
                unsigned r[4];
                ldsm4(r, sw_hi + off);
                bh[2*ntp][0] = r[0]; bh[2*ntp+1][0] = r[1];
                bh[2*ntp][1] = r[2]; bh[2*ntp+1][1] = r[3];
                ldsm4(r, sw_lo + off);
                bl[2*ntp][0] = r[0]; bl[2*ntp+1][0] = r[1];
                bl[2*ntp][1] = r[2]; bl[2*ntp+1][1] = r[3];
            }
#pragma unroll
            for (int mt = 0; mt < 4; mt++)
#pragma unroll
                for (int nt = 0; nt < 4; nt++) {
                    mma16816(acc[mt][nt], ah[mt], bh[nt]);
                    mma16816(acc[mt][nt], ah[mt], bl[nt]);
                    mma16816(acc[mt][nt], al[mt], bh[nt]);
                }
        }

        if (c + 1 < HIDN / 32) {
            __syncthreads();
            store_chunk();
            __syncthreads();
        }
    }

    // Epilogue: direct register -> global with bias (+ optional QKV scatter)
    const int g = lane >> 2, t = lane & 3;
#pragma unroll
    for (int mt = 0; mt < 4; mt++) {
#pragma unroll
        for (int nt = 0; nt < 4; nt++) {
            const int n = bn * 128 + wn * 32 + nt * 8 + 2 * t;
            const float2 bi = *(const float2*)(bias + n);
            const int m0 = bm * 128 + wm * 64 + mt * 16 + g;
#pragma unroll
            for (int half = 0; half < 2; half++) {
                const int m = m0 + half * 8;
                float2 v;
                v.x = acc[mt][nt][half * 2 + 0] + bi.x;
                v.y = acc[mt][nt][half * 2 + 1] + bi.y;
                if (!scatter) {
                    *(float2*)(C + (size_t)m * HIDN + n) = v;
                } else {
                    const int b = m >> 11, s = m & 2047;   // SEQ = 2048
                    const int h = n >> 6,  d = n & 63;     // HD  = 64
                    *(float2*)(C + (((size_t)(b * HEADS + h)) * SEQ + s) * HD + d) = v;
                }
            }
        }
    }
}

// ---------------------------------------------------------------------------
// Block-causal flash attention (unchanged). One CTA per (qblk, h, b).
// ---------------------------------------------------------------------------
#define ATTN_SMEM_FLOATS (64*64 + 64*65 + 64*65)
#define ATTN_SMEM_BYTES  (ATTN_SMEM_FLOATS * 4)

__global__ __launch_bounds__(256) void attn_kernel(
    const float* __restrict__ Q, const float* __restrict__ K,
    const float* __restrict__ V, float* __restrict__ O)
{
    extern __shared__ float smemf[];
    float* Qs = smemf;
    float* Ks = smemf + 64 * 64;
    float* Ps = Ks + 64 * 65;

    const int qb = blockIdx.x;
    const int h  = blockIdx.y;
    const int b  = blockIdx.z;
    const int tid = threadIdx.x;
    const int ty = tid >> 4;
    const int tx = tid & 15;

    const size_t hb = ((size_t)(b * HEADS + h)) * SEQ * HD;
    const float scale = 0.125f;

    {
        const float* Qg = Q + hb + (size_t)qb * 64 * HD;
        for (int p = tid; p < 1024; p += 256) {
            const int r = p >> 4, c = (p & 15) << 2;
            float4 v = *(const float4*)(Qg + r * HD + c);
            float* dst = Qs + r * 64 + c;
            dst[0] = v.x * scale; dst[1] = v.y * scale;
            dst[2] = v.z * scale; dst[3] = v.w * scale;
        }
    }

    float m_i[4], l_i[4], o[4][4];
#pragma unroll
    for (int i = 0; i < 4; i++) {
        m_i[i] = -1e30f; l_i[i] = 0.f;
#pragma unroll
        for (int c = 0; c < 4; c++) o[i][c] = 0.f;
    }

    for (int kb = 0; kb <= qb; kb++) {
        __syncthreads();
        {
            const float* Kg = K + hb + (size_t)kb * 64 * HD;
            for (int p = tid; p < 1024; p += 256) {
                const int r = p >> 4, c = (p & 15) << 2;
                float4 v = *(const float4*)(Kg + r * HD + c);
                float* dst = Ks + r * 65 + c;
                dst[0] = v.x; dst[1] = v.y; dst[2] = v.z; dst[3] = v.w;
            }
        }
        __syncthreads();

        float sacc[4][4];
#pragma unroll
        for (int i = 0; i < 4; i++)
#pragma unroll
            for (int j = 0; j < 4; j++) sacc[i][j] = 0.f;

#pragma unroll 4
        for (int dd = 0; dd < 64; dd++) {
            float qv[4], kv[4];
#pragma unroll
            for (int i = 0; i < 4; i++) qv[i] = Qs[(ty * 4 + i) * 64 + dd];
#pragma unroll
            for (int j = 0; j < 4; j++) kv[j] = Ks[(tx * 4 + j) * 65 + dd];
#pragma unroll
            for (int i = 0; i < 4; i++)
#pragma unroll
                for (int j = 0; j < 4; j++)
                    sacc[i][j] += qv[i] * kv[j];
        }

#pragma unroll
        for (int i = 0; i < 4; i++) {
            float mt = fmaxf(fmaxf(sacc[i][0], sacc[i][1]),
                             fmaxf(sacc[i][2], sacc[i][3]));
#pragma unroll
            for (int off = 8; off >= 1; off >>= 1)
                mt = fmaxf(mt, __shfl_xor_sync(0xffffffffu, mt, off));
            const float mnew = fmaxf(m_i[i], mt);
            const float corr = __expf(m_i[i] - mnew);
            float ls = 0.f;
#pragma unroll
            for (int j = 0; j < 4; j++) {
                const float pv = __expf(sacc[i][j] - mnew);
                sacc[i][j] = pv;
                ls += pv;
            }
#pragma unroll
            for (int off = 8; off >= 1; off >>= 1)
                ls += __shfl_xor_sync(0xffffffffu, ls, off);
            l_i[i] = l_i[i] * corr + ls;
            m_i[i] = mnew;
#pragma unroll
            for (int c = 0; c < 4; c++) o[i][c] *= corr;
#pragma unroll
            for (int j = 0; j < 4; j++)
                Ps[(ty * 4 + i) * 65 + tx * 4 + j] = sacc[i][j];
        }
        __syncthreads();

        {
            const float* Vg = V + hb + (size_t)kb * 64 * HD;
            for (int p = tid; p < 1024; p += 256) {
                const int r = p >> 4, c = (p & 15) << 2;
                float4 v = *(const float4*)(Vg + r * HD + c);
                float* dst = Ks + r * 65 + c;
                dst[0] = v.x; dst[1] = v.y; dst[2] = v.z; dst[3] = v.w;
            }
        }
        __syncthreads();

#pragma unroll 4
        for (int j = 0; j < 64; j++) {
            float pv[4], vv[4];
#pragma unroll
            for (int i = 0; i < 4; i++) pv[i] = Ps[(ty * 4 + i) * 65 + j];
#pragma unroll
            for (int c = 0; c < 4; c++) vv[c] = Ks[j * 65 + tx * 4 + c];
#pragma unroll
            for (int i = 0; i < 4; i++)
#pragma unroll
                for (int c = 0; c < 4; c++)
                    o[i][c] += pv[i] * vv[c];
        }
    }

#pragma unroll
    for (int i = 0; i < 4; i++) {
        const float inv = 1.f / l_i[i];
        const int srow = b * SEQ + qb * 64 + ty * 4 + i;
#pragma unroll
        for (int c = 0; c < 4; c++) {
            O[(size_t)srow * HIDN + h * HD + tx * 4 + c] = o[i][c] * inv;
        }
    }
}

// ---------------------------------------------------------------------------
extern "C" void kernel_launch(void* const* d_in, const int* in_sizes, int n_in,
                              void* d_out, int out_size)
{
    const float* x  = (const float*)d_in[0];
    const float* Wq = (const float*)d_in[1];
    const float* bq = (const float*)d_in[2];
    const float* Wk = (const float*)d_in[3];
    const float* bk = (const float*)d_in[4];
    const float* Wv = (const float*)d_in[5];
    const float* bv = (const float*)d_in[6];
    const float* Wo = (const float*)d_in[7];
    const float* bo = (const float*)d_in[8];
    float* out = (float*)d_out;

    float *q, *k, *v, *attn;
    cudaGetSymbolAddress((void**)&q,    g_q);
    cudaGetSymbolAddress((void**)&k,    g_k);
    cudaGetSymbolAddress((void**)&v,    g_v);
    cudaGetSymbolAddress((void**)&attn, g_attn);

    cudaFuncSetAttribute(gemm_mma_kernel,
                         cudaFuncAttributeMaxDynamicSharedMemorySize, GSM_BYTES);
    cudaFuncSetAttribute(attn_kernel,
                         cudaFuncAttributeMaxDynamicSharedMemorySize,
                         ATTN_SMEM_BYTES);

    dim3 ggrid(HIDN / 128, MROWS / 128);   // (8, 32)

    gemm_mma_kernel<<<ggrid, 256, GSM_BYTES>>>(x, Wq, bq, q, 1);
    gemm_mma_kernel<<<ggrid, 256, GSM_BYTES>>>(x, Wk, bk, k, 1);
    gemm_mma_kernel<<<ggrid, 256, GSM_BYTES>>>(x, Wv, bv, v, 1);

    attn_kernel<<<dim3(NQB, HEADS, BSZ), 256, ATTN_SMEM_BYTES>>>(q, k, v, attn);

    gemm_mma_kernel<<<ggrid, 256, GSM_BYTES>>>(attn, Wo, bo, out, 0);
}

// round 6
// speedup vs baseline: 2.1977x; 1.5300x over previous
#include <cuda_runtime.h>
#include <cuda_bf16.h>

// Problem constants
#define BSZ   2
#define SEQ   2048
#define HIDN  1024
#define HEADS 16
#define HD    64
#define NQB   32            // SEQ / 64
#define MROWS (BSZ*SEQ)     // 4096

// Scratch (device globals)
__device__ float g_q[BSZ*HEADS*SEQ*HD];     // [B,H,S,D]
__device__ float g_k[BSZ*HEADS*SEQ*HD];
__device__ float g_v[BSZ*HEADS*SEQ*HD];
__device__ float g_attn[BSZ*SEQ*HIDN];      // [B,S,HID]

// ===========================================================================
// mma.sync helpers (base-PTX, works on target sm_103)
// ===========================================================================
__device__ __forceinline__ unsigned smem_u32(const void* p) {
    unsigned a;
    asm("{ .reg .u64 t; cvta.to.shared.u64 t, %1; cvt.u32.u64 %0, t; }"
        : "=r"(a) : "l"(p));
    return a;
}

__device__ __forceinline__ void ldsm4(unsigned* r, unsigned addr) {
    asm volatile("ldmatrix.sync.aligned.m8n8.x4.shared.b16 {%0,%1,%2,%3}, [%4];"
                 : "=r"(r[0]), "=r"(r[1]), "=r"(r[2]), "=r"(r[3]) : "r"(addr));
}

__device__ __forceinline__ void ldsm4t(unsigned* r, unsigned addr) {
    asm volatile("ldmatrix.sync.aligned.m8n8.x4.trans.shared.b16 {%0,%1,%2,%3}, [%4];"
                 : "=r"(r[0]), "=r"(r[1]), "=r"(r[2]), "=r"(r[3]) : "r"(addr));
}

__device__ __forceinline__ void mma16816(float* c, const unsigned* a,
                                         const unsigned* b) {
    asm volatile(
        "mma.sync.aligned.m16n8k16.row.col.f32.bf16.bf16.f32 "
        "{%0,%1,%2,%3}, {%4,%5,%6,%7}, {%8,%9}, {%0,%1,%2,%3};"
        : "+f"(c[0]), "+f"(c[1]), "+f"(c[2]), "+f"(c[3])
        : "r"(a[0]), "r"(a[1]), "r"(a[2]), "r"(a[3]), "r"(b[0]), "r"(b[1]));
}

__device__ __forceinline__ unsigned pack_bf16(__nv_bfloat16 x, __nv_bfloat16 y) {
    return ((unsigned)__bfloat16_as_ushort(y) << 16) | __bfloat16_as_ushort(x);
}

// split a float4 into hi/lo bf16 pairs and store (2 u32 each)
__device__ __forceinline__ void split4(__nv_bfloat16* hi, __nv_bfloat16* lo,
                                       int e, float4 x) {
    __nv_bfloat16 h0 = __float2bfloat16_rn(x.x);
    __nv_bfloat16 h1 = __float2bfloat16_rn(x.y);
    __nv_bfloat16 h2 = __float2bfloat16_rn(x.z);
    __nv_bfloat16 h3 = __float2bfloat16_rn(x.w);
    *(unsigned*)(hi + e)     = pack_bf16(h0, h1);
    *(unsigned*)(hi + e + 2) = pack_bf16(h2, h3);
    *(unsigned*)(lo + e)     = pack_bf16(
        __float2bfloat16_rn(x.x - __bfloat162float(h0)),
        __float2bfloat16_rn(x.y - __bfloat162float(h1)));
    *(unsigned*)(lo + e + 2) = pack_bf16(
        __float2bfloat16_rn(x.z - __bfloat162float(h2)),
        __float2bfloat16_rn(x.w - __bfloat162float(h3)));
}

// ===========================================================================
// GEMM (unchanged from R5): C = A @ W^T + bias, bf16 3-split mma.sync.
// ===========================================================================
#define GS_STRIDE 40
#define GS_TILE   (128 * GS_STRIDE)
#define GSM_BYTES (4 * GS_TILE * 2)

__global__ __launch_bounds__(256, 1)
void gemm_mma_kernel(const float* __restrict__ A, const float* __restrict__ W,
                     const float* __restrict__ bias, float* __restrict__ C,
                     int scatter)
{
    extern __shared__ char gsm[];
    __nv_bfloat16* a_hi = (__nv_bfloat16*)gsm;
    __nv_bfloat16* a_lo = a_hi + GS_TILE;
    __nv_bfloat16* w_hi = a_lo + GS_TILE;
    __nv_bfloat16* w_lo = w_hi + GS_TILE;

    const int tid  = threadIdx.x;
    const int lane = tid & 31;
    const int wid  = tid >> 5;
    const int wm   = wid >> 2;
    const int wn   = wid & 3;
    const int bn = blockIdx.x, bm = blockIdx.y;

    const float* Ag = A + (size_t)bm * 128 * HIDN;
    const float* Wg = W + (size_t)bn * 128 * HIDN;

    const int lr  = tid >> 3;
    const int lc4 = (tid & 7) << 2;

    float4 va[4], vb[4];

    auto load_chunk = [&](int kt) {
#pragma unroll
        for (int i = 0; i < 4; i++) {
            const int r = lr + i * 32;
            va[i] = *(const float4*)(Ag + (size_t)r * HIDN + kt + lc4);
            vb[i] = *(const float4*)(Wg + (size_t)r * HIDN + kt + lc4);
        }
    };

    auto store_chunk = [&]() {
#pragma unroll
        for (int i = 0; i < 4; i++) {
            const int r = lr + i * 32;
            const int e = r * GS_STRIDE + lc4;
            split4(a_hi, a_lo, e, va[i]);
            split4(w_hi, w_lo, e, vb[i]);
        }
    };

    float acc[4][4][4];
#pragma unroll
    for (int i = 0; i < 4; i++)
#pragma unroll
        for (int j = 0; j < 4; j++)
#pragma unroll
            for (int k = 0; k < 4; k++) acc[i][j][k] = 0.f;

    const int fr = lane & 15;
    const int fc = (lane >> 4) << 3;
    const unsigned sa_hi = smem_u32(a_hi);
    const unsigned sa_lo = smem_u32(a_lo);
    const unsigned sw_hi = smem_u32(w_hi);
    const unsigned sw_lo = smem_u32(w_lo);

    load_chunk(0);
    store_chunk();
    __syncthreads();

    for (int c = 0; c < HIDN / 32; c++) {
        if (c + 1 < HIDN / 32) load_chunk((c + 1) * 32);

#pragma unroll
        for (int ks = 0; ks < 2; ks++) {
            const int kcol = ks * 16 + fc;
            unsigned ah[4][4], al[4][4], bh[4][2], bl[4][2];
#pragma unroll
            for (int mt = 0; mt < 4; mt++) {
                const unsigned off =
                    ((wm * 64 + mt * 16 + fr) * GS_STRIDE + kcol) * 2;
                ldsm4(ah[mt], sa_hi + off);
                ldsm4(al[mt], sa_lo + off);
            }
#pragma unroll
            for (int ntp = 0; ntp < 2; ntp++) {
                const unsigned off =
                    ((wn * 32 + ntp * 16 + fr) * GS_STRIDE + kcol) * 2;
                unsigned r[4];
                ldsm4(r, sw_hi + off);
                bh[2*ntp][0] = r[0]; bh[2*ntp+1][0] = r[1];
                bh[2*ntp][1] = r[2]; bh[2*ntp+1][1] = r[3];
                ldsm4(r, sw_lo + off);
                bl[2*ntp][0] = r[0]; bl[2*ntp+1][0] = r[1];
                bl[2*ntp][1] = r[2]; bl[2*ntp+1][1] = r[3];
            }
#pragma unroll
            for (int mt = 0; mt < 4; mt++)
#pragma unroll
                for (int nt = 0; nt < 4; nt++) {
                    mma16816(acc[mt][nt], ah[mt], bh[nt]);
                    mma16816(acc[mt][nt], ah[mt], bl[nt]);
                    mma16816(acc[mt][nt], al[mt], bh[nt]);
                }
        }

        if (c + 1 < HIDN / 32) {
            __syncthreads();
            store_chunk();
            __syncthreads();
        }
    }

    const int g = lane >> 2, t = lane & 3;
#pragma unroll
    for (int mt = 0; mt < 4; mt++) {
#pragma unroll
        for (int nt = 0; nt < 4; nt++) {
            const int n = bn * 128 + wn * 32 + nt * 8 + 2 * t;
            const float2 bi = *(const float2*)(bias + n);
            const int m0 = bm * 128 + wm * 64 + mt * 16 + g;
#pragma unroll
            for (int half = 0; half < 2; half++) {
                const int m = m0 + half * 8;
                float2 v;
                v.x = acc[mt][nt][half * 2 + 0] + bi.x;
                v.y = acc[mt][nt][half * 2 + 1] + bi.y;
                if (!scatter) {
                    *(float2*)(C + (size_t)m * HIDN + n) = v;
                } else {
                    const int b = m >> 11, s = m & 2047;
                    const int h = n >> 6,  d = n & 63;
                    *(float2*)(C + (((size_t)(b * HEADS + h)) * SEQ + s) * HD + d) = v;
                }
            }
        }
    }
}

// ===========================================================================
// Block-causal flash attention on mma.sync (bf16 3-split everywhere).
// One CTA per (q-block 64, head, batch); 8 warps in 4x2 grid:
//   wm = wid>>1 (16-row group), wn = wid&1 (32-col group).
// SMEM bf16 tiles stride 72: Qh Ql Kh Kl Vh Vl Ph Pl; S fp32 stride 66;
// per-row state m/l/corr.
// ===========================================================================
#define AST 72
#define ATILE (64 * AST)                       // bf16 elems per tile
#define SS_STRIDE 66
#define AOFF_S   (8 * ATILE * 2)               // byte offset of S tile
#define AOFF_ROW (AOFF_S + 64 * SS_STRIDE * 4)
#define ATTN_SMEM (AOFF_ROW + 3 * 64 * 4)      // ~91.4 KB

__global__ __launch_bounds__(256)
void attn_mma_kernel(const float* __restrict__ Q, const float* __restrict__ K,
                     const float* __restrict__ V, float* __restrict__ O)
{
    extern __shared__ char asmem[];
    __nv_bfloat16* sQh = (__nv_bfloat16*)asmem;
    __nv_bfloat16* sQl = sQh + ATILE;
    __nv_bfloat16* sKh = sQl + ATILE;
    __nv_bfloat16* sKl = sKh + ATILE;
    __nv_bfloat16* sVh = sKl + ATILE;
    __nv_bfloat16* sVl = sVh + ATILE;
    __nv_bfloat16* sPh = sVl + ATILE;
    __nv_bfloat16* sPl = sPh + ATILE;
    float* Ss   = (float*)(asmem + AOFF_S);
    float* rowm = (float*)(asmem + AOFF_ROW);
    float* rowl = rowm + 64;
    float* rowc = rowl + 64;

    const int qb = blockIdx.x, h = blockIdx.y, b = blockIdx.z;
    const int tid  = threadIdx.x;
    const int lane = tid & 31;
    const int wid  = tid >> 5;
    const int wm   = wid >> 1;                 // 0..3
    const int wn   = wid & 1;                  // 0..1
    const int fr = lane & 15, fc = (lane >> 4) << 3;
    const int g  = lane >> 2, t = lane & 3;

    const size_t hb = ((size_t)(b * HEADS + h)) * SEQ * HD;
    const float scale = 0.125f;

    const unsigned uQh = smem_u32(sQh), uQl = smem_u32(sQl);
    const unsigned uKh = smem_u32(sKh), uKl = smem_u32(sKl);
    const unsigned uVh = smem_u32(sVh), uVl = smem_u32(sVl);
    const unsigned uPh = smem_u32(sPh), uPl = smem_u32(sPl);

    if (tid < 64) { rowm[tid] = -1e30f; rowl[tid] = 0.f; }

    // Load + scale + split Q
    {
        const float* Qg = Q + hb + (size_t)qb * 64 * HD;
        for (int p = tid; p < 1024; p += 256) {
            const int r = p >> 4, c = (p & 15) << 2;
            float4 v = *(const float4*)(Qg + r * HD + c);
            v.x *= scale; v.y *= scale; v.z *= scale; v.w *= scale;
            split4(sQh, sQl, r * AST + c, v);
        }
    }
    __syncthreads();

    float o_acc[4][4];
#pragma unroll
    for (int i = 0; i < 4; i++)
#pragma unroll
        for (int j = 0; j < 4; j++) o_acc[i][j] = 0.f;

    for (int kb = 0; kb <= qb; kb++) {
        if (kb) __syncthreads();   // protect K/V/P/S reuse

        // Stage K and V tiles (fp32 -> bf16 hi/lo)
        {
            const float* Kg = K + hb + (size_t)kb * 64 * HD;
            const float* Vg = V + hb + (size_t)kb * 64 * HD;
            for (int p = tid; p < 1024; p += 256) {
                const int r = p >> 4, c = (p & 15) << 2;
                split4(sKh, sKl, r * AST + c, *(const float4*)(Kg + r * HD + c));
                split4(sVh, sVl, r * AST + c, *(const float4*)(Vg + r * HD + c));
            }
        }
        __syncthreads();

        // S = Q K^T (3-split)
        float sfr[4][4];
#pragma unroll
        for (int i = 0; i < 4; i++)
#pragma unroll
            for (int j = 0; j < 4; j++) sfr[i][j] = 0.f;

#pragma unroll
        for (int ks = 0; ks < 4; ks++) {
            const int kcol = ks * 16 + fc;
            unsigned ah[4], al[4];
            const unsigned offa = ((wm * 16 + fr) * AST + kcol) * 2;
            ldsm4(ah, uQh + offa);
            ldsm4(al, uQl + offa);
#pragma unroll
            for (int ntp = 0; ntp < 2; ntp++) {
                const unsigned offb = ((wn * 32 + ntp * 16 + fr) * AST + kcol) * 2;
                unsigned rh[4], rl[4];
                ldsm4(rh, uKh + offb);
                ldsm4(rl, uKl + offb);
                unsigned bh0[2] = {rh[0], rh[2]}, bh1[2] = {rh[1], rh[3]};
                unsigned bl0[2] = {rl[0], rl[2]}, bl1[2] = {rl[1], rl[3]};
                mma16816(sfr[2*ntp],   ah, bh0);
                mma16816(sfr[2*ntp],   ah, bl0);
                mma16816(sfr[2*ntp],   al, bh0);
                mma16816(sfr[2*ntp+1], ah, bh1);
                mma16816(sfr[2*ntp+1], ah, bl1);
                mma16816(sfr[2*ntp+1], al, bh1);
            }
        }

        // Stage S to SMEM (fp32)
#pragma unroll
        for (int nt = 0; nt < 4; nt++) {
            const int col = wn * 32 + nt * 8 + 2 * t;
            *(float2*)(Ss + (wm * 16 + g)     * SS_STRIDE + col) =
                make_float2(sfr[nt][0], sfr[nt][1]);
            *(float2*)(Ss + (wm * 16 + g + 8) * SS_STRIDE + col) =
                make_float2(sfr[nt][2], sfr[nt][3]);
        }
        __syncthreads();

        // Softmax: 4 threads per row, 16 cols each
        {
            const int r  = tid >> 2;
            const int q4 = (tid & 3) << 4;
            float sv[16];
#pragma unroll
            for (int i = 0; i < 16; i++) sv[i] = Ss[r * SS_STRIDE + q4 + i];
            float mt = sv[0];
#pragma unroll
            for (int i = 1; i < 16; i++) mt = fmaxf(mt, sv[i]);
            mt = fmaxf(mt, __shfl_xor_sync(0xffffffffu, mt, 1));
            mt = fmaxf(mt, __shfl_xor_sync(0xffffffffu, mt, 2));
            const float mprev = rowm[r];
            const float mnew  = fmaxf(mprev, mt);
            float ls = 0.f;
#pragma unroll
            for (int i = 0; i < 16; i += 2) {
                float p0 = __expf(sv[i]   - mnew);
                float p1 = __expf(sv[i+1] - mnew);
                ls += p0 + p1;
                __nv_bfloat16 h0 = __float2bfloat16_rn(p0);
                __nv_bfloat16 h1 = __float2bfloat16_rn(p1);
                *(unsigned*)(sPh + r * AST + q4 + i) = pack_bf16(h0, h1);
                *(unsigned*)(sPl + r * AST + q4 + i) = pack_bf16(
                    __float2bfloat16_rn(p0 - __bfloat162float(h0)),
                    __float2bfloat16_rn(p1 - __bfloat162float(h1)));
            }
            ls += __shfl_xor_sync(0xffffffffu, ls, 1);
            ls += __shfl_xor_sync(0xffffffffu, ls, 2);
            if ((tid & 3) == 0) {
                const float corr = __expf(mprev - mnew);
                rowm[r] = mnew;
                rowl[r] = rowl[r] * corr + ls;
                rowc[r] = corr;
            }
        }
        __syncthreads();

        // Rescale O accumulators
        {
            const float c0 = rowc[wm * 16 + g];
            const float c1 = rowc[wm * 16 + g + 8];
#pragma unroll
            for (int nt = 0; nt < 4; nt++) {
                o_acc[nt][0] *= c0; o_acc[nt][1] *= c0;
                o_acc[nt][2] *= c1; o_acc[nt][3] *= c1;
            }
        }

        // O += P V (3-split); V via ldmatrix.trans from [k][d] layout
        const int vkr = ((lane >> 4) << 3) + (lane & 7);   // k row within 16
        const int vnc = ((lane >> 3) & 1) << 3;            // n col half
#pragma unroll
        for (int ks = 0; ks < 4; ks++) {
            unsigned ah[4], al[4];
            const unsigned offa = ((wm * 16 + fr) * AST + ks * 16 + fc) * 2;
            ldsm4(ah, uPh + offa);
            ldsm4(al, uPl + offa);
#pragma unroll
            for (int ntp = 0; ntp < 2; ntp++) {
                const unsigned offv =
                    ((ks * 16 + vkr) * AST + wn * 32 + ntp * 16 + vnc) * 2;
                unsigned rh[4], rl[4];
                ldsm4t(rh, uVh + offv);
                ldsm4t(rl, uVl + offv);
                unsigned bh0[2] = {rh[0], rh[2]}, bh1[2] = {rh[1], rh[3]};
                unsigned bl0[2] = {rl[0], rl[2]}, bl1[2] = {rl[1], rl[3]};
                mma16816(o_acc[2*ntp],   ah, bh0);
                mma16816(o_acc[2*ntp],   ah, bl0);
                mma16816(o_acc[2*ntp],   al, bh0);
                mma16816(o_acc[2*ntp+1], ah, bh1);
                mma16816(o_acc[2*ntp+1], ah, bl1);
                mma16816(o_acc[2*ntp+1], al, bh1);
            }
        }
    }

    // Finalize: O /= l, write [B,S,HID]
    {
        const float li0 = 1.f / rowl[wm * 16 + g];
        const float li1 = 1.f / rowl[wm * 16 + g + 8];
        const int row0 = b * SEQ + qb * 64 + wm * 16 + g;
#pragma unroll
        for (int nt = 0; nt < 4; nt++) {
            const int col = h * HD + wn * 32 + nt * 8 + 2 * t;
            *(float2*)(O + (size_t)row0 * HIDN + col) =
                make_float2(o_acc[nt][0] * li0, o_acc[nt][1] * li0);
            *(float2*)(O + (size_t)(row0 + 8) * HIDN + col) =
                make_float2(o_acc[nt][2] * li1, o_acc[nt][3] * li1);
        }
    }
}

// ---------------------------------------------------------------------------
extern "C" void kernel_launch(void* const* d_in, const int* in_sizes, int n_in,
                              void* d_out, int out_size)
{
    const float* x  = (const float*)d_in[0];
    const float* Wq = (const float*)d_in[1];
    const float* bq = (const float*)d_in[2];
    const float* Wk = (const float*)d_in[3];
    const float* bk = (const float*)d_in[4];
    const float* Wv = (const float*)d_in[5];
    const float* bv = (const float*)d_in[6];
    const float* Wo = (const float*)d_in[7];
    const float* bo = (const float*)d_in[8];
    float* out = (float*)d_out;

    float *q, *k, *v, *attn;
    cudaGetSymbolAddress((void**)&q,    g_q);
    cudaGetSymbolAddress((void**)&k,    g_k);
    cudaGetSymbolAddress((void**)&v,    g_v);
    cudaGetSymbolAddress((void**)&attn, g_attn);

    cudaFuncSetAttribute(gemm_mma_kernel,
                         cudaFuncAttributeMaxDynamicSharedMemorySize, GSM_BYTES);
    cudaFuncSetAttribute(attn_mma_kernel,
                         cudaFuncAttributeMaxDynamicSharedMemorySize, ATTN_SMEM);

    dim3 ggrid(HIDN / 128, MROWS / 128);   // (8, 32)

    gemm_mma_kernel<<<ggrid, 256, GSM_BYTES>>>(x, Wq, bq, q, 1);
    gemm_mma_kernel<<<ggrid, 256, GSM_BYTES>>>(x, Wk, bk, k, 1);
    gemm_mma_kernel<<<ggrid, 256, GSM_BYTES>>>(x, Wv, bv, v, 1);

    attn_mma_kernel<<<dim3(NQB, HEADS, BSZ), 256, ATTN_SMEM>>>(q, k, v, attn);

    gemm_mma_kernel<<<ggrid, 256, GSM_BYTES>>>(attn, Wo, bo, out, 0);
}

// round 9
// speedup vs baseline: 2.5282x; 1.1504x over previous
#include <cuda_runtime.h>
#include <cuda_bf16.h>

// Problem constants
#define BSZ   2
#define SEQ   2048
#define HIDN  1024
#define HEADS 16
#define HD    64
#define NQB   32            // SEQ / 64
#define MROWS (BSZ*SEQ)     // 4096

typedef __nv_bfloat16 bf16;

// Scratch (device globals)
__device__ bf16 g_xh[MROWS*HIDN], g_xl[MROWS*HIDN];
__device__ bf16 g_w8[8][HIDN*HIDN];       // Wq h,l  Wk h,l  Wv h,l  Wo h,l
__device__ bf16 g_qh[BSZ*HEADS*SEQ*HD], g_ql[BSZ*HEADS*SEQ*HD];
__device__ bf16 g_kh[BSZ*HEADS*SEQ*HD], g_kl[BSZ*HEADS*SEQ*HD];
__device__ bf16 g_vh[BSZ*HEADS*SEQ*HD], g_vl[BSZ*HEADS*SEQ*HD];
__device__ bf16 g_ah[MROWS*HIDN], g_al[MROWS*HIDN];   // attn out [B,S,HID]

// ===========================================================================
// helpers
// ===========================================================================
__device__ __forceinline__ unsigned smem_u32(const void* p) {
    unsigned a;
    asm("{ .reg .u64 t; cvta.to.shared.u64 t, %1; cvt.u32.u64 %0, t; }"
        : "=r"(a) : "l"(p));
    return a;
}
__device__ __forceinline__ void ldsm4(unsigned* r, unsigned addr) {
    asm volatile("ldmatrix.sync.aligned.m8n8.x4.shared.b16 {%0,%1,%2,%3}, [%4];"
                 : "=r"(r[0]), "=r"(r[1]), "=r"(r[2]), "=r"(r[3]) : "r"(addr));
}
__device__ __forceinline__ void ldsm4t(unsigned* r, unsigned addr) {
    asm volatile("ldmatrix.sync.aligned.m8n8.x4.trans.shared.b16 {%0,%1,%2,%3}, [%4];"
                 : "=r"(r[0]), "=r"(r[1]), "=r"(r[2]), "=r"(r[3]) : "r"(addr));
}
__device__ __forceinline__ void mma16816(float* c, const unsigned* a,
                                         const unsigned* b) {
    asm volatile(
        "mma.sync.aligned.m16n8k16.row.col.f32.bf16.bf16.f32 "
        "{%0,%1,%2,%3}, {%4,%5,%6,%7}, {%8,%9}, {%0,%1,%2,%3};"
        : "+f"(c[0]), "+f"(c[1]), "+f"(c[2]), "+f"(c[3])
        : "r"(a[0]), "r"(a[1]), "r"(a[2]), "r"(a[3]), "r"(b[0]), "r"(b[1]));
}
__device__ __forceinline__ unsigned pack_bf16(bf16 x, bf16 y) {
    return ((unsigned)__bfloat16_as_ushort(y) << 16) | __bfloat16_as_ushort(x);
}
#define CP_ASYNC16(dst, src) \
    asm volatile("cp.async.cg.shared.global [%0], [%1], 16;" :: "r"(dst), "l"(src))
#define CP_COMMIT() asm volatile("cp.async.commit_group;" ::: "memory")
#define CP_WAIT0()  asm volatile("cp.async.wait_group 0;" ::: "memory")

// ===========================================================================
// split kernel: fp32 -> bf16 hi/lo
// ===========================================================================
__global__ void split_kernel(const float* __restrict__ src,
                             bf16* __restrict__ hi, bf16* __restrict__ lo,
                             int n4)
{
    const int i = blockIdx.x * blockDim.x + threadIdx.x;
    if (i >= n4) return;
    float4 v = ((const float4*)src)[i];
    bf16 h0 = __float2bfloat16_rn(v.x);
    bf16 h1 = __float2bfloat16_rn(v.y);
    bf16 h2 = __float2bfloat16_rn(v.z);
    bf16 h3 = __float2bfloat16_rn(v.w);
    uint2 ho, lo2;
    ho.x = pack_bf16(h0, h1); ho.y = pack_bf16(h2, h3);
    lo2.x = pack_bf16(__float2bfloat16_rn(v.x - __bfloat162float(h0)),
                      __float2bfloat16_rn(v.y - __bfloat162float(h1)));
    lo2.y = pack_bf16(__float2bfloat16_rn(v.z - __bfloat162float(h2)),
                      __float2bfloat16_rn(v.w - __bfloat162float(h3)));
    ((uint2*)hi)[i] = ho;
    ((uint2*)lo)[i] = lo2;
}

// ===========================================================================
// GEMM: C = A @ W^T + bias, A/W pre-split bf16 hi/lo, cp.async 2-stage.
// ===========================================================================
#define GST       40
#define GTILE_B   (128 * GST * 2)        // 10240 B per tile
#define GSTAGE_B  (4 * GTILE_B)          // 40960 B
#define GSM_BYTES (2 * GSTAGE_B)         // 81920 B

__global__ __launch_bounds__(256)
void gemm_mma2(const bf16* __restrict__ Ah, const bf16* __restrict__ Al,
               const bf16* __restrict__ Wh, const bf16* __restrict__ Wl,
               const float* __restrict__ bias,
               float* __restrict__ Cf, bf16* __restrict__ Oh,
               bf16* __restrict__ Ol, float scl, int scatter)
{
    extern __shared__ char sm[];
    const int tid  = threadIdx.x;
    const int lane = tid & 31;
    const int wid  = tid >> 5;
    const int wm   = wid >> 2;           // 0..1
    const int wn   = wid & 3;            // 0..3
    const int bn = blockIdx.x, bm = blockIdx.y;

    const bf16* gsrc[4];
    gsrc[0] = Ah + (size_t)bm * 128 * HIDN;
    gsrc[1] = Al + (size_t)bm * 128 * HIDN;
    gsrc[2] = Wh + (size_t)bn * 128 * HIDN;
    gsrc[3] = Wl + (size_t)bn * 128 * HIDN;

    auto issue = [&](int c) {
        char* st = sm + (c & 1) * GSTAGE_B;
        const int kt = c * 32;
#pragma unroll
        for (int t4 = 0; t4 < 4; t4++) {
#pragma unroll
            for (int j = 0; j < 2; j++) {
                const int ch = tid + j * 256;
                const int row = ch >> 2, cc = ch & 3;
                unsigned dst = smem_u32(st + t4 * GTILE_B + (row * GST + cc * 8) * 2);
                const bf16* src = gsrc[t4] + (size_t)row * HIDN + kt + cc * 8;
                CP_ASYNC16(dst, src);
            }
        }
        CP_COMMIT();
    };

    issue(0);

    float acc[4][4][4];
#pragma unroll
    for (int i = 0; i < 4; i++)
#pragma unroll
        for (int j = 0; j < 4; j++)
#pragma unroll
            for (int k = 0; k < 4; k++) acc[i][j][k] = 0.f;

    const int fr = lane & 15;
    const int fc = (lane >> 4) << 3;

    for (int c = 0; c < HIDN / 32; c++) {
        CP_WAIT0();
        __syncthreads();
        if (c + 1 < HIDN / 32) issue(c + 1);

        const unsigned sb = smem_u32(sm) + (c & 1) * GSTAGE_B;
        const unsigned uAh = sb, uAl = sb + GTILE_B;
        const unsigned uWh = sb + 2 * GTILE_B, uWl = sb + 3 * GTILE_B;

#pragma unroll
        for (int ks = 0; ks < 2; ks++) {
            const int kcol = ks * 16 + fc;
            unsigned ah[4][4], al[4][4], bh[4][2], bl[4][2];
#pragma unroll
            for (int mt = 0; mt < 4; mt++) {
                const unsigned off = ((wm * 64 + mt * 16 + fr) * GST + kcol) * 2;
                ldsm4(ah[mt], uAh + off);
                ldsm4(al[mt], uAl + off);
            }
#pragma unroll
            for (int ntp = 0; ntp < 2; ntp++) {
                const unsigned off = ((wn * 32 + ntp * 16 + fr) * GST + kcol) * 2;
                unsigned r[4];
                ldsm4(r, uWh + off);
                bh[2*ntp][0] = r[0]; bh[2*ntp+1][0] = r[1];
                bh[2*ntp][1] = r[2]; bh[2*ntp+1][1] = r[3];
                ldsm4(r, uWl + off);
                bl[2*ntp][0] = r[0]; bl[2*ntp+1][0] = r[1];
                bl[2*ntp][1] = r[2]; bl[2*ntp+1][1] = r[3];
            }
#pragma unroll
            for (int mt = 0; mt < 4; mt++)
#pragma unroll
                for (int nt = 0; nt < 4; nt++) {
                    mma16816(acc[mt][nt], ah[mt], bh[nt]);
                    mma16816(acc[mt][nt], ah[mt], bl[nt]);
                    mma16816(acc[mt][nt], al[mt], bh[nt]);
                }
        }
    }

    const int g = lane >> 2, t = lane & 3;
#pragma unroll
    for (int mt = 0; mt < 4; mt++) {
#pragma unroll
        for (int nt = 0; nt < 4; nt++) {
            const int n = bn * 128 + wn * 32 + nt * 8 + 2 * t;
            const float2 bi = *(const float2*)(bias + n);
            const int m0 = bm * 128 + wm * 64 + mt * 16 + g;
#pragma unroll
            for (int half = 0; half < 2; half++) {
                const int m = m0 + half * 8;
                float vx = (acc[mt][nt][half * 2 + 0] + bi.x) * scl;
                float vy = (acc[mt][nt][half * 2 + 1] + bi.y) * scl;
                if (!scatter) {
                    *(float2*)(Cf + (size_t)m * HIDN + n) = make_float2(vx, vy);
                } else {
                    const int b = m >> 11, s = m & 2047;
                    const int h = n >> 6,  d = n & 63;
                    const size_t idx =
                        (((size_t)(b * HEADS + h)) * SEQ + s) * HD + d;
                    bf16 h0 = __float2bfloat16_rn(vx);
                    bf16 h1 = __float2bfloat16_rn(vy);
                    *(unsigned*)(Oh + idx) = pack_bf16(h0, h1);
                    *(unsigned*)(Ol + idx) = pack_bf16(
                        __float2bfloat16_rn(vx - __bfloat162float(h0)),
                        __float2bfloat16_rn(vy - __bfloat162float(h1)));
                }
            }
        }
    }
}

// ===========================================================================
// Block-causal flash attention, pre-split inputs, cp.async K/V double-buffer,
// register-resident online softmax.
// ===========================================================================
#define AST     72
#define ATILE_B (64 * AST * 2)            // 9216 B
#define AOFF_STAGE 18432
#define AOFF_XM  (AOFF_STAGE + 2 * 4 * ATILE_B)
#define AOFF_XL  (AOFF_XM + 512)
#define ATTN_SMEM (AOFF_XL + 512)         // 93184 B

__global__ __launch_bounds__(256, 2)
void attn_mma2(const bf16* __restrict__ gqh, const bf16* __restrict__ gql,
               const bf16* __restrict__ gkh, const bf16* __restrict__ gkl,
               const bf16* __restrict__ gvh, const bf16* __restrict__ gvl,
               bf16* __restrict__ goh, bf16* __restrict__ gol)
{
    extern __shared__ char sm[];
    const int qb = NQB - 1 - blockIdx.x;
    const int h = blockIdx.y, b = blockIdx.z;
    const int tid  = threadIdx.x;
    const int lane = tid & 31;
    const int wid  = tid >> 5;
    const int wm   = wid >> 1;
    const int wn   = wid & 1;
    const int fr = lane & 15, fc = (lane >> 4) << 3;
    const int g  = lane >> 2, t = lane & 3;
    const int vkr = ((lane >> 4) << 3) + (lane & 7);
    const int vnc = ((lane >> 3) & 1) << 3;

    const size_t hb = ((size_t)(b * HEADS + h)) * SEQ * HD;
    const bf16* src_k[4];
    src_k[0] = gkh + hb; src_k[1] = gkl + hb;
    src_k[2] = gvh + hb; src_k[3] = gvl + hb;

    auto issueKV = [&](int kb) {
        char* st = sm + AOFF_STAGE + (kb & 1) * 4 * ATILE_B;
        const size_t koff = (size_t)kb * 64 * HD;
#pragma unroll
        for (int t4 = 0; t4 < 4; t4++) {
#pragma unroll
            for (int j = 0; j < 2; j++) {
                const int ch = tid + j * 256;
                const int row = ch >> 3, cc = ch & 7;
                unsigned dst = smem_u32(st + t4 * ATILE_B + (row * AST + cc * 8) * 2);
                const bf16* src = src_k[t4] + koff + row * HD + cc * 8;
                CP_ASYNC16(dst, src);
            }
        }
        CP_COMMIT();
    };

    issueKV(0);

    {
        const bf16* qh = gqh + hb + (size_t)qb * 64 * HD;
        const bf16* ql = gql + hb + (size_t)qb * 64 * HD;
#pragma unroll
        for (int j = 0; j < 2; j++) {
            const int ch = tid + j * 256;
            const int row = ch >> 3, cc = ch & 7;
            *(uint4*)(sm + (row * AST + cc * 8) * 2) =
                *(const uint4*)(qh + row * HD + cc * 8);
            *(uint4*)(sm + ATILE_B + (row * AST + cc * 8) * 2) =
                *(const uint4*)(ql + row * HD + cc * 8);
        }
    }

    const unsigned uQh = smem_u32(sm), uQl = uQh + ATILE_B;
    float* xm = (float*)(sm + AOFF_XM);
    float* xl = (float*)(sm + AOFF_XL);

    float o_acc[8][4];
#pragma unroll
    for (int i = 0; i < 8; i++)
#pragma unroll
        for (int j = 0; j < 4; j++) o_acc[i][j] = 0.f;
    float m0r = -1e30f, m1r = -1e30f, l0r = 0.f, l1r = 0.f;

    for (int kb = 0; kb <= qb; kb++) {
        CP_WAIT0();
        __syncthreads();
        if (kb + 1 <= qb) issueKV(kb + 1);

        const unsigned us = smem_u32(sm) + AOFF_STAGE + (kb & 1) * 4 * ATILE_B;
        const unsigned uKh = us, uKl = us + ATILE_B;
        const unsigned uVh = us + 2 * ATILE_B, uVl = us + 3 * ATILE_B;

        float sfr[4][4];
#pragma unroll
        for (int i = 0; i < 4; i++)
#pragma unroll
            for (int j = 0; j < 4; j++) sfr[i][j] = 0.f;

#pragma unroll
        for (int ks = 0; ks < 4; ks++) {
            const int kcol = ks * 16 + fc;
            unsigned qa_h[4], qa_l[4];
            const unsigned offa = ((wm * 16 + fr) * AST + kcol) * 2;
            ldsm4(qa_h, uQh + offa);
            ldsm4(qa_l, uQl + offa);
#pragma unroll
            for (int ntp = 0; ntp < 2; ntp++) {
                const unsigned offb = ((wn * 32 + ntp * 16 + fr) * AST + kcol) * 2;
                unsigned rh[4], rl[4];
                ldsm4(rh, uKh + offb);
                ldsm4(rl, uKl + offb);
                unsigned bh0[2] = {rh[0], rh[2]}, bh1[2] = {rh[1], rh[3]};
                unsigned bl0[2] = {rl[0], rl[2]}, bl1[2] = {rl[1], rl[3]};
                mma16816(sfr[2*ntp],   qa_h, bh0);
                mma16816(sfr[2*ntp],   qa_h, bl0);
                mma16816(sfr[2*ntp],   qa_l, bh0);
                mma16816(sfr[2*ntp+1], qa_h, bh1);
                mma16816(sfr[2*ntp+1], qa_h, bl1);
                mma16816(sfr[2*ntp+1], qa_l, bh1);
            }
        }

        // register softmax
        float pm0 = sfr[0][0], pm1 = sfr[0][2];
#pragma unroll
        for (int nt = 0; nt < 4; nt++) {
            pm0 = fmaxf(pm0, fmaxf(sfr[nt][0], sfr[nt][1]));
            pm1 = fmaxf(pm1, fmaxf(sfr[nt][2], sfr[nt][3]));
        }
        pm0 = fmaxf(pm0, __shfl_xor_sync(0xffffffffu, pm0, 1));
        pm0 = fmaxf(pm0, __shfl_xor_sync(0xffffffffu, pm0, 2));
        pm1 = fmaxf(pm1, __shfl_xor_sync(0xffffffffu, pm1, 1));
        pm1 = fmaxf(pm1, __shfl_xor_sync(0xffffffffu, pm1, 2));

        float ps0 = 0.f, ps1 = 0.f;
#pragma unroll
        for (int nt = 0; nt < 4; nt++) {
            sfr[nt][0] = __expf(sfr[nt][0] - pm0);
            sfr[nt][1] = __expf(sfr[nt][1] - pm0);
            sfr[nt][2] = __expf(sfr[nt][2] - pm1);
            sfr[nt][3] = __expf(sfr[nt][3] - pm1);
            ps0 += sfr[nt][0] + sfr[nt][1];
            ps1 += sfr[nt][2] + sfr[nt][3];
        }
        ps0 += __shfl_xor_sync(0xffffffffu, ps0, 1);
        ps0 += __shfl_xor_sync(0xffffffffu, ps0, 2);
        ps1 += __shfl_xor_sync(0xffffffffu, ps1, 1);
        ps1 += __shfl_xor_sync(0xffffffffu, ps1, 2);

        if (t == 0) {
            xm[wn * 64 + wm * 16 + g]     = pm0;
            xm[wn * 64 + wm * 16 + g + 8] = pm1;
            xl[wn * 64 + wm * 16 + g]     = ps0;
            xl[wn * 64 + wm * 16 + g + 8] = ps1;
        }
        __syncthreads();

        const int r0 = wm * 16 + g;
        const float ma0 = xm[r0],    mb0 = xm[64 + r0];
        const float la0 = xl[r0],    lb0 = xl[64 + r0];
        const float ma1 = xm[r0+8],  mb1 = xm[64 + r0 + 8];
        const float la1 = xl[r0+8],  lb1 = xl[64 + r0 + 8];
        const float mt0 = fmaxf(ma0, mb0), mt1 = fmaxf(ma1, mb1);
        const float lt0 = la0 * __expf(ma0 - mt0) + lb0 * __expf(mb0 - mt0);
        const float lt1 = la1 * __expf(ma1 - mt1) + lb1 * __expf(mb1 - mt1);

        const float mnew0 = fmaxf(m0r, mt0), mnew1 = fmaxf(m1r, mt1);
        const float corr0 = __expf(m0r - mnew0), corr1 = __expf(m1r - mnew1);
        l0r = l0r * corr0 + lt0 * __expf(mt0 - mnew0);
        l1r = l1r * corr1 + lt1 * __expf(mt1 - mnew1);
        m0r = mnew0; m1r = mnew1;

        const float pf0 = __expf(pm0 - mnew0), pf1 = __expf(pm1 - mnew1);
#pragma unroll
        for (int nt = 0; nt < 4; nt++) {
            sfr[nt][0] *= pf0; sfr[nt][1] *= pf0;
            sfr[nt][2] *= pf1; sfr[nt][3] *= pf1;
        }
#pragma unroll
        for (int n8 = 0; n8 < 8; n8++) {
            o_acc[n8][0] *= corr0; o_acc[n8][1] *= corr0;
            o_acc[n8][2] *= corr1; o_acc[n8][3] *= corr1;
        }

        // P -> A fragments (bf16 hi/lo) in registers
        unsigned pa_h[2][4], pa_l[2][4];
#pragma unroll
        for (int ks2 = 0; ks2 < 2; ks2++) {
            const int ntA = 2 * ks2, ntB = 2 * ks2 + 1;
            const float p00 = sfr[ntA][0], p01 = sfr[ntA][1];
            const float p02 = sfr[ntA][2], p03 = sfr[ntA][3];
            const float p10 = sfr[ntB][0], p11 = sfr[ntB][1];
            const float p12 = sfr[ntB][2], p13 = sfr[ntB][3];
            const bf16 h00 = __float2bfloat16_rn(p00), h01 = __float2bfloat16_rn(p01);
            const bf16 h02 = __float2bfloat16_rn(p02), h03 = __float2bfloat16_rn(p03);
            const bf16 h10 = __float2bfloat16_rn(p10), h11 = __float2bfloat16_rn(p11);
            const bf16 h12 = __float2bfloat16_rn(p12), h13 = __float2bfloat16_rn(p13);
            pa_h[ks2][0] = pack_bf16(h00, h01);
            pa_h[ks2][1] = pack_bf16(h02, h03);
            pa_h[ks2][2] = pack_bf16(h10, h11);
            pa_h[ks2][3] = pack_bf16(h12, h13);
            pa_l[ks2][0] = pack_bf16(
                __float2bfloat16_rn(p00 - __bfloat162float(h00)),
                __float2bfloat16_rn(p01 - __bfloat162float(h01)));
            pa_l[ks2][1] = pack_bf16(
                __float2bfloat16_rn(p02 - __bfloat162float(h02)),
                __float2bfloat16_rn(p03 - __bfloat162float(h03)));
            pa_l[ks2][2] = pack_bf16(
                __float2bfloat16_rn(p10 - __bfloat162float(h10)),
                __float2bfloat16_rn(p11 - __bfloat162float(h11)));
            pa_l[ks2][3] = pack_bf16(
                __float2bfloat16_rn(p12 - __bfloat162float(h12)),
                __float2bfloat16_rn(p13 - __bfloat162float(h13)));
        }

        // O += P V  (this warp's k-half)
#pragma unroll
        for (int ks2 = 0; ks2 < 2; ks2++) {
#pragma unroll
            for (int nc = 0; nc < 4; nc++) {
                const unsigned offv =
                    ((wn * 32 + ks2 * 16 + vkr) * AST + nc * 16 + vnc) * 2;
                unsigned rh[4], rl[4];
                ldsm4t(rh, uVh + offv);
                ldsm4t(rl, uVl + offv);
                unsigned bh0[2] = {rh[0], rh[2]}, bh1[2] = {rh[1], rh[3]};
                unsigned bl0[2] = {rl[0], rl[2]}, bl1[2] = {rl[1], rl[3]};
                mma16816(o_acc[nc*2],   pa_h[ks2], bh0);
                mma16816(o_acc[nc*2],   pa_h[ks2], bl0);
                mma16816(o_acc[nc*2],   pa_l[ks2], bh0);
                mma16816(o_acc[nc*2+1], pa_h[ks2], bh1);
                mma16816(o_acc[nc*2+1], pa_h[ks2], bl1);
                mma16816(o_acc[nc*2+1], pa_l[ks2], bh1);
            }
        }
        __syncthreads();
    }

    // cross-warp O reduction + split output
    float* red = (float*)(sm + AOFF_STAGE);     // [64][66]
    if (wn == 1) {
#pragma unroll
        for (int n8 = 0; n8 < 8; n8++) {
            const int col = n8 * 8 + 2 * t;
            red[(wm * 16 + g)     * 66 + col]     = o_acc[n8][0];
            red[(wm * 16 + g)     * 66 + col + 1] = o_acc[n8][1];
            red[(wm * 16 + g + 8) * 66 + col]     = o_acc[n8][2];
            red[(wm * 16 + g + 8) * 66 + col + 1] = o_acc[n8][3];
        }
    }
    __syncthreads();
    if (wn == 0) {
        const float inv0 = 1.f / l0r, inv1 = 1.f / l1r;
        const size_t obase = ((size_t)(b * SEQ + qb * 64)) * HIDN + h * HD;
#pragma unroll
        for (int n8 = 0; n8 < 8; n8++) {
            const int col = n8 * 8 + 2 * t;
            const float v0 = (o_acc[n8][0] + red[(wm*16+g)*66 + col])     * inv0;
            const float v1 = (o_acc[n8][1] + red[(wm*16+g)*66 + col + 1]) * inv0;
            const float v2 = (o_acc[n8][2] + red[(wm*16+g+8)*66 + col])     * inv1;
            const float v3 = (o_acc[n8][3] + red[(wm*16+g+8)*66 + col + 1]) * inv1;
            const bf16 h0 = __float2bfloat16_rn(v0), h1 = __float2bfloat16_rn(v1);
            const bf16 h2 = __float2bfloat16_rn(v2), h3 = __float2bfloat16_rn(v3);
            const size_t i0 = obase + (size_t)(wm * 16 + g) * HIDN + col;
            const size_t i1 = obase + (size_t)(wm * 16 + g + 8) * HIDN + col;
            *(unsigned*)(goh + i0) = pack_bf16(h0, h1);
            *(unsigned*)(gol + i0) = pack_bf16(
                __float2bfloat16_rn(v0 - __bfloat162float(h0)),
                __float2bfloat16_rn(v1 - __bfloat162float(h1)));
            *(unsigned*)(goh + i1) = pack_bf16(h2, h3);
            *(unsigned*)(gol + i1) = pack_bf16(
                __float2bfloat16_rn(v2 - __bfloat162float(h2)),
                __float2bfloat16_rn(v3 - __bfloat162float(h3)));
        }
    }
}

// ---------------------------------------------------------------------------
extern "C" void kernel_launch(void* const* d_in, const int* in_sizes, int n_in,
                              void* d_out, int out_size)
{
    const float* x  = (const float*)d_in[0];
    const float* Wq = (const float*)d_in[1];
    const float* bq = (const float*)d_in[2];
    const float* Wk = (const float*)d_in[3];
    const float* bk = (const float*)d_in[4];
    const float* Wv = (const float*)d_in[5];
    const float* bv = (const float*)d_in[6];
    const float* Wo = (const float*)d_in[7];
    const float* bo = (const float*)d_in[8];
    float* out = (float*)d_out;

    bf16 *xh, *xl, *w8, *qh, *ql, *kh, *kl, *vh, *vl, *ah, *al;
    cudaGetSymbolAddress((void**)&xh, g_xh);
    cudaGetSymbolAddress((void**)&xl, g_xl);
    cudaGetSymbolAddress((void**)&w8, g_w8);
    cudaGetSymbolAddress((void**)&qh, g_qh);
    cudaGetSymbolAddress((void**)&ql, g_ql);
    cudaGetSymbolAddress((void**)&kh, g_kh);
    cudaGetSymbolAddress((void**)&kl, g_kl);
    cudaGetSymbolAddress((void**)&vh, g_vh);
    cudaGetSymbolAddress((void**)&vl, g_vl);
    cudaGetSymbolAddress((void**)&ah, g_ah);
    cudaGetSymbolAddress((void**)&al, g_al);

    cudaFuncSetAttribute(gemm_mma2,
                         cudaFuncAttributeMaxDynamicSharedMemorySize, GSM_BYTES);
    cudaFuncSetAttribute(attn_mma2,
                         cudaFuncAttributeMaxDynamicSharedMemorySize, ATTN_SMEM);

    const int W2 = HIDN * HIDN;

    split_kernel<<<(MROWS*HIDN/4 + 255)/256, 256>>>(x, xh, xl, MROWS*HIDN/4);
    split_kernel<<<(W2/4 + 255)/256, 256>>>(Wq, w8 + 0*W2, w8 + 1*W2, W2/4);
    split_kernel<<<(W2/4 + 255)/256, 256>>>(Wk, w8 + 2*W2, w8 + 3*W2, W2/4);
    split_kernel<<<(W2/4 + 255)/256, 256>>>(Wv, w8 + 4*W2, w8 + 5*W2, W2/4);
    split_kernel<<<(W2/4 + 255)/256, 256>>>(Wo, w8 + 6*W2, w8 + 7*W2, W2/4);

    dim3 ggrid(HIDN / 128, MROWS / 128);

    gemm_mma2<<<ggrid, 256, GSM_BYTES>>>(xh, xl, w8 + 0*W2, w8 + 1*W2, bq,
                                         nullptr, qh, ql, 0.125f, 1);
    gemm_mma2<<<ggrid, 256, GSM_BYTES>>>(xh, xl, w8 + 2*W2, w8 + 3*W2, bk,
                                         nullptr, kh, kl, 1.0f, 1);
    gemm_mma2<<<ggrid, 256, GSM_BYTES>>>(xh, xl, w8 + 4*W2, w8 + 5*W2, bv,
                                         nullptr, vh, vl, 1.0f, 1);

    attn_mma2<<<dim3(NQB, HEADS, BSZ), 256, ATTN_SMEM>>>(qh, ql, kh, kl,
                                                         vh, vl, ah, al);

    gemm_mma2<<<ggrid, 256, GSM_BYTES>>>(ah, al, w8 + 6*W2, w8 + 7*W2, bo,
                                         out, nullptr, nullptr, 1.0f, 0);
}

// round 10
// speedup vs baseline: 2.7020x; 1.0687x over previous
#include <cuda_runtime.h>
#include <cuda_bf16.h>

// Problem constants
#define BSZ   2
#define SEQ   2048
#define HIDN  1024
#define HEADS 16
#define HD    64
#define NQB   32            // SEQ / 64
#define MROWS (BSZ*SEQ)     // 4096

typedef __nv_bfloat16 bf16;

// Scratch (device globals)
__device__ bf16 g_xh[MROWS*HIDN], g_xl[MROWS*HIDN];
__device__ bf16 g_w8[8][HIDN*HIDN];       // Wq h,l  Wk h,l  Wv h,l  Wo h,l
__device__ bf16 g_qh[BSZ*HEADS*SEQ*HD], g_ql[BSZ*HEADS*SEQ*HD];
__device__ bf16 g_kh[BSZ*HEADS*SEQ*HD], g_kl[BSZ*HEADS*SEQ*HD];
__device__ bf16 g_vh[BSZ*HEADS*SEQ*HD], g_vl[BSZ*HEADS*SEQ*HD];
__device__ bf16 g_ah[MROWS*HIDN], g_al[MROWS*HIDN];   // attn out [B,S,HID]

// ===========================================================================
// helpers
// ===========================================================================
__device__ __forceinline__ unsigned smem_u32(const void* p) {
    unsigned a;
    asm("{ .reg .u64 t; cvta.to.shared.u64 t, %1; cvt.u32.u64 %0, t; }"
        : "=r"(a) : "l"(p));
    return a;
}
__device__ __forceinline__ void ldsm4(unsigned* r, unsigned addr) {
    asm volatile("ldmatrix.sync.aligned.m8n8.x4.shared.b16 {%0,%1,%2,%3}, [%4];"
                 : "=r"(r[0]), "=r"(r[1]), "=r"(r[2]), "=r"(r[3]) : "r"(addr));
}
__device__ __forceinline__ void ldsm4t(unsigned* r, unsigned addr) {
    asm volatile("ldmatrix.sync.aligned.m8n8.x4.trans.shared.b16 {%0,%1,%2,%3}, [%4];"
                 : "=r"(r[0]), "=r"(r[1]), "=r"(r[2]), "=r"(r[3]) : "r"(addr));
}
__device__ __forceinline__ void mma16816(float* c, const unsigned* a,
                                         const unsigned* b) {
    asm volatile(
        "mma.sync.aligned.m16n8k16.row.col.f32.bf16.bf16.f32 "
        "{%0,%1,%2,%3}, {%4,%5,%6,%7}, {%8,%9}, {%0,%1,%2,%3};"
        : "+f"(c[0]), "+f"(c[1]), "+f"(c[2]), "+f"(c[3])
        : "r"(a[0]), "r"(a[1]), "r"(a[2]), "r"(a[3]), "r"(b[0]), "r"(b[1]));
}
__device__ __forceinline__ unsigned pack_bf16(bf16 x, bf16 y) {
    return ((unsigned)__bfloat16_as_ushort(y) << 16) | __bfloat16_as_ushort(x);
}
#define CP_ASYNC16(dst, src) \
    asm volatile("cp.async.cg.shared.global [%0], [%1], 16;" :: "r"(dst), "l"(src))
#define CP_COMMIT() asm volatile("cp.async.commit_group;" ::: "memory")
#define CP_WAIT0()  asm volatile("cp.async.wait_group 0;" ::: "memory")
#define CP_WAIT1()  asm volatile("cp.async.wait_group 1;" ::: "memory")

// ===========================================================================
// split kernel: fp32 -> bf16 hi/lo (2 independent float4s per thread)
// ===========================================================================
__global__ void split_kernel(const float* __restrict__ src,
                             bf16* __restrict__ hi, bf16* __restrict__ lo,
                             int n4)
{
    const int base = (blockIdx.x * blockDim.x + threadIdx.x) * 2;
    if (base >= n4) return;
    float4 va = ((const float4*)src)[base];
    float4 vb = ((const float4*)src)[base + 1];
#pragma unroll
    for (int u = 0; u < 2; u++) {
        const float4 v = u ? vb : va;
        const int i = base + u;
        bf16 h0 = __float2bfloat16_rn(v.x);
        bf16 h1 = __float2bfloat16_rn(v.y);
        bf16 h2 = __float2bfloat16_rn(v.z);
        bf16 h3 = __float2bfloat16_rn(v.w);
        uint2 ho, lo2;
        ho.x = pack_bf16(h0, h1); ho.y = pack_bf16(h2, h3);
        lo2.x = pack_bf16(__float2bfloat16_rn(v.x - __bfloat162float(h0)),
                          __float2bfloat16_rn(v.y - __bfloat162float(h1)));
        lo2.y = pack_bf16(__float2bfloat16_rn(v.z - __bfloat162float(h2)),
                          __float2bfloat16_rn(v.w - __bfloat162float(h3)));
        ((uint2*)hi)[i] = ho;
        ((uint2*)lo)[i] = lo2;
    }
}

// ===========================================================================
// GEMM: C = A @ W^T + bias, pre-split bf16 hi/lo, BK=64, 3-stage cp.async.
// BM=BN=128, 8 warps (2x4), warp tile 64x32, bf16 3-split MMA.
// ===========================================================================
#define GST       72
#define GTILE_B   (128 * GST * 2)        // 18432 B per tile
#define GSTAGE_B  (4 * GTILE_B)          // 73728 B
#define GSM_BYTES (3 * GSTAGE_B)         // 221184 B
#define NCHUNK    (HIDN / 64)            // 16

__global__ __launch_bounds__(256)
void gemm_mma3(const bf16* __restrict__ Ah, const bf16* __restrict__ Al,
               const bf16* __restrict__ Wh, const bf16* __restrict__ Wl,
               const float* __restrict__ bias,
               float* __restrict__ Cf, bf16* __restrict__ Oh,
               bf16* __restrict__ Ol, float scl, int scatter)
{
    extern __shared__ char sm[];
    const int tid  = threadIdx.x;
    const int lane = tid & 31;
    const int wid  = tid >> 5;
    const int wm   = wid >> 2;           // 0..1
    const int wn   = wid & 3;            // 0..3
    const int bn = blockIdx.x, bm = blockIdx.y;

    const bf16* gsrc[4];
    gsrc[0] = Ah + (size_t)bm * 128 * HIDN;
    gsrc[1] = Al + (size_t)bm * 128 * HIDN;
    gsrc[2] = Wh + (size_t)bn * 128 * HIDN;
    gsrc[3] = Wl + (size_t)bn * 128 * HIDN;

    auto issue = [&](int c) {
        char* st = sm + (c % 3) * GSTAGE_B;
        const int kt = c * 64;
#pragma unroll
        for (int t4 = 0; t4 < 4; t4++) {
#pragma unroll
            for (int j = 0; j < 4; j++) {
                const int ch = tid + j * 256;      // 0..1023
                const int row = ch >> 3, cc = ch & 7;
                unsigned dst = smem_u32(st + t4 * GTILE_B + (row * GST + cc * 8) * 2);
                const bf16* src = gsrc[t4] + (size_t)row * HIDN + kt + cc * 8;
                CP_ASYNC16(dst, src);
            }
        }
        CP_COMMIT();
    };

    issue(0);
    issue(1);

    float acc[4][4][4];
#pragma unroll
    for (int i = 0; i < 4; i++)
#pragma unroll
        for (int j = 0; j < 4; j++)
#pragma unroll
            for (int k = 0; k < 4; k++) acc[i][j][k] = 0.f;

    const int fr = lane & 15;
    const int fc = (lane >> 4) << 3;

    for (int c = 0; c < NCHUNK; c++) {
        CP_WAIT1();              // chunk c resident (c+1 may be in flight)
        __syncthreads();         // all warps done with buffer (c+2)%3's prior use
        if (c + 2 < NCHUNK) issue(c + 2);

        const unsigned sb = smem_u32(sm) + (c % 3) * GSTAGE_B;
        const unsigned uAh = sb, uAl = sb + GTILE_B;
        const unsigned uWh = sb + 2 * GTILE_B, uWl = sb + 3 * GTILE_B;

#pragma unroll
        for (int ks = 0; ks < 4; ks++) {
            const int kcol = ks * 16 + fc;
            unsigned ah[4][4], al[4][4], bh[4][2], bl[4][2];
#pragma unroll
            for (int mt = 0; mt < 4; mt++) {
                const unsigned off = ((wm * 64 + mt * 16 + fr) * GST + kcol) * 2;
                ldsm4(ah[mt], uAh + off);
                ldsm4(al[mt], uAl + off);
            }
#pragma unroll
            for (int ntp = 0; ntp < 2; ntp++) {
                const unsigned off = ((wn * 32 + ntp * 16 + fr) * GST + kcol) * 2;
                unsigned r[4];
                ldsm4(r, uWh + off);
                bh[2*ntp][0] = r[0]; bh[2*ntp+1][0] = r[1];
                bh[2*ntp][1] = r[2]; bh[2*ntp+1][1] = r[3];
                ldsm4(r, uWl + off);
                bl[2*ntp][0] = r[0]; bl[2*ntp+1][0] = r[1];
                bl[2*ntp][1] = r[2]; bl[2*ntp+1][1] = r[3];
            }
#pragma unroll
            for (int mt = 0; mt < 4; mt++)
#pragma unroll
                for (int nt = 0; nt < 4; nt++) {
                    mma16816(acc[mt][nt], ah[mt], bh[nt]);
                    mma16816(acc[mt][nt], ah[mt], bl[nt]);
                    mma16816(acc[mt][nt], al[mt], bh[nt]);
                }
        }
    }

    const int g = lane >> 2, t = lane & 3;
#pragma unroll
    for (int mt = 0; mt < 4; mt++) {
#pragma unroll
        for (int nt = 0; nt < 4; nt++) {
            const int n = bn * 128 + wn * 32 + nt * 8 + 2 * t;
            const float2 bi = *(const float2*)(bias + n);
            const int m0 = bm * 128 + wm * 64 + mt * 16 + g;
#pragma unroll
            for (int half = 0; half < 2; half++) {
                const int m = m0 + half * 8;
                float vx = (acc[mt][nt][half * 2 + 0] + bi.x) * scl;
                float vy = (acc[mt][nt][half * 2 + 1] + bi.y) * scl;
                if (!scatter) {
                    *(float2*)(Cf + (size_t)m * HIDN + n) = make_float2(vx, vy);
                } else {
                    const int b = m >> 11, s = m & 2047;
                    const int h = n >> 6,  d = n & 63;
                    const size_t idx =
                        (((size_t)(b * HEADS + h)) * SEQ + s) * HD + d;
                    bf16 h0 = __float2bfloat16_rn(vx);
                    bf16 h1 = __float2bfloat16_rn(vy);
                    *(unsigned*)(Oh + idx) = pack_bf16(h0, h1);
                    *(unsigned*)(Ol + idx) = pack_bf16(
                        __float2bfloat16_rn(vx - __bfloat162float(h0)),
                        __float2bfloat16_rn(vy - __bfloat162float(h1)));
                }
            }
        }
    }
}

// ===========================================================================
// Block-causal flash attention: pre-split inputs, cp.async KV double-buffer,
// register softmax, double-buffered m/l exchange (2 syncs/iter).
// ===========================================================================
#define AST     72
#define ATILE_B (64 * AST * 2)            // 9216 B
#define AOFF_STAGE 18432
#define AOFF_XM  (AOFF_STAGE + 2 * 4 * ATILE_B)   // 92160
#define ATTN_SMEM (AOFF_XM + 2048)        // 94208 B

__global__ __launch_bounds__(256, 2)
void attn_mma2(const bf16* __restrict__ gqh, const bf16* __restrict__ gql,
               const bf16* __restrict__ gkh, const bf16* __restrict__ gkl,
               const bf16* __restrict__ gvh, const bf16* __restrict__ gvl,
               bf16* __restrict__ goh, bf16* __restrict__ gol)
{
    extern __shared__ char sm[];
    const int qb = NQB - 1 - blockIdx.x;
    const int h = blockIdx.y, b = blockIdx.z;
    const int tid  = threadIdx.x;
    const int lane = tid & 31;
    const int wid  = tid >> 5;
    const int wm   = wid >> 1;
    const int wn   = wid & 1;
    const int fr = lane & 15, fc = (lane >> 4) << 3;
    const int g  = lane >> 2, t = lane & 3;
    const int vkr = ((lane >> 4) << 3) + (lane & 7);
    const int vnc = ((lane >> 3) & 1) << 3;

    const size_t hb = ((size_t)(b * HEADS + h)) * SEQ * HD;
    const bf16* src_k[4];
    src_k[0] = gkh + hb; src_k[1] = gkl + hb;
    src_k[2] = gvh + hb; src_k[3] = gvl + hb;

    auto issueKV = [&](int kb) {
        char* st = sm + AOFF_STAGE + (kb & 1) * 4 * ATILE_B;
        const size_t koff = (size_t)kb * 64 * HD;
#pragma unroll
        for (int t4 = 0; t4 < 4; t4++) {
#pragma unroll
            for (int j = 0; j < 2; j++) {
                const int ch = tid + j * 256;
                const int row = ch >> 3, cc = ch & 7;
                unsigned dst = smem_u32(st + t4 * ATILE_B + (row * AST + cc * 8) * 2);
                const bf16* src = src_k[t4] + koff + row * HD + cc * 8;
                CP_ASYNC16(dst, src);
            }
        }
        CP_COMMIT();
    };

    issueKV(0);

    {
        const bf16* qh = gqh + hb + (size_t)qb * 64 * HD;
        const bf16* ql = gql + hb + (size_t)qb * 64 * HD;
#pragma unroll
        for (int j = 0; j < 2; j++) {
            const int ch = tid + j * 256;
            const int row = ch >> 3, cc = ch & 7;
            *(uint4*)(sm + (row * AST + cc * 8) * 2) =
                *(const uint4*)(qh + row * HD + cc * 8);
            *(uint4*)(sm + ATILE_B + (row * AST + cc * 8) * 2) =
                *(const uint4*)(ql + row * HD + cc * 8);
        }
    }

    const unsigned uQh = smem_u32(sm), uQl = uQh + ATILE_B;

    float o_acc[8][4];
#pragma unroll
    for (int i = 0; i < 8; i++)
#pragma unroll
        for (int j = 0; j < 4; j++) o_acc[i][j] = 0.f;
    float m0r = -1e30f, m1r = -1e30f, l0r = 0.f, l1r = 0.f;

    for (int kb = 0; kb <= qb; kb++) {
        CP_WAIT0();
        __syncthreads();
        if (kb + 1 <= qb) issueKV(kb + 1);

        float* xm = (float*)(sm + AOFF_XM + (kb & 1) * 512);
        float* xl = (float*)(sm + AOFF_XM + 1024 + (kb & 1) * 512);

        const unsigned us = smem_u32(sm) + AOFF_STAGE + (kb & 1) * 4 * ATILE_B;
        const unsigned uKh = us, uKl = us + ATILE_B;
        const unsigned uVh = us + 2 * ATILE_B, uVl = us + 3 * ATILE_B;

        float sfr[4][4];
#pragma unroll
        for (int i = 0; i < 4; i++)
#pragma unroll
            for (int j = 0; j < 4; j++) sfr[i][j] = 0.f;

#pragma unroll
        for (int ks = 0; ks < 4; ks++) {
            const int kcol = ks * 16 + fc;
            unsigned qa_h[4], qa_l[4];
            const unsigned offa = ((wm * 16 + fr) * AST + kcol) * 2;
            ldsm4(qa_h, uQh + offa);
            ldsm4(qa_l, uQl + offa);
#pragma unroll
            for (int ntp = 0; ntp < 2; ntp++) {
                const unsigned offb = ((wn * 32 + ntp * 16 + fr) * AST + kcol) * 2;
                unsigned rh[4], rl[4];
                ldsm4(rh, uKh + offb);
                ldsm4(rl, uKl + offb);
                unsigned bh0[2] = {rh[0], rh[2]}, bh1[2] = {rh[1], rh[3]};
                unsigned bl0[2] = {rl[0], rl[2]}, bl1[2] = {rl[1], rl[3]};
                mma16816(sfr[2*ntp],   qa_h, bh0);
                mma16816(sfr[2*ntp],   qa_h, bl0);
                mma16816(sfr[2*ntp],   qa_l, bh0);
                mma16816(sfr[2*ntp+1], qa_h, bh1);
                mma16816(sfr[2*ntp+1], qa_h, bl1);
                mma16816(sfr[2*ntp+1], qa_l, bh1);
            }
        }

        // register softmax
        float pm0 = sfr[0][0], pm1 = sfr[0][2];
#pragma unroll
        for (int nt = 0; nt < 4; nt++) {
            pm0 = fmaxf(pm0, fmaxf(sfr[nt][0], sfr[nt][1]));
            pm1 = fmaxf(pm1, fmaxf(sfr[nt][2], sfr[nt][3]));
        }
        pm0 = fmaxf(pm0, __shfl_xor_sync(0xffffffffu, pm0, 1));
        pm0 = fmaxf(pm0, __shfl_xor_sync(0xffffffffu, pm0, 2));
        pm1 = fmaxf(pm1, __shfl_xor_sync(0xffffffffu, pm1, 1));
        pm1 = fmaxf(pm1, __shfl_xor_sync(0xffffffffu, pm1, 2));

        float ps0 = 0.f, ps1 = 0.f;
#pragma unroll
        for (int nt = 0; nt < 4; nt++) {
            sfr[nt][0] = __expf(sfr[nt][0] - pm0);
            sfr[nt][1] = __expf(sfr[nt][1] - pm0);
            sfr[nt][2] = __expf(sfr[nt][2] - pm1);
            sfr[nt][3] = __expf(sfr[nt][3] - pm1);
            ps0 += sfr[nt][0] + sfr[nt][1];
            ps1 += sfr[nt][2] + sfr[nt][3];
        }
        ps0 += __shfl_xor_sync(0xffffffffu, ps0, 1);
        ps0 += __shfl_xor_sync(0xffffffffu, ps0, 2);
        ps1 += __shfl_xor_sync(0xffffffffu, ps1, 1);
        ps1 += __shfl_xor_sync(0xffffffffu, ps1, 2);

        if (t == 0) {
            xm[wn * 64 + wm * 16 + g]     = pm0;
            xm[wn * 64 + wm * 16 + g + 8] = pm1;
            xl[wn * 64 + wm * 16 + g]     = ps0;
            xl[wn * 64 + wm * 16 + g + 8] = ps1;
        }
        __syncthreads();

        const int r0 = wm * 16 + g;
        const float ma0 = xm[r0],    mb0 = xm[64 + r0];
        const float la0 = xl[r0],    lb0 = xl[64 + r0];
        const float ma1 = xm[r0+8],  mb1 = xm[64 + r0 + 8];
        const float la1 = xl[r0+8],  lb1 = xl[64 + r0 + 8];
        const float mt0 = fmaxf(ma0, mb0), mt1 = fmaxf(ma1, mb1);
        const float lt0 = la0 * __expf(ma0 - mt0) + lb0 * __expf(mb0 - mt0);
        const float lt1 = la1 * __expf(ma1 - mt1) + lb1 * __expf(mb1 - mt1);

        const float mnew0 = fmaxf(m0r, mt0), mnew1 = fmaxf(m1r, mt1);
        const float corr0 = __expf(m0r - mnew0), corr1 = __expf(m1r - mnew1);
        l0r = l0r * corr0 + lt0 * __expf(mt0 - mnew0);
        l1r = l1r * corr1 + lt1 * __expf(mt1 - mnew1);
        m0r = mnew0; m1r = mnew1;

        const float pf0 = __expf(pm0 - mnew0), pf1 = __expf(pm1 - mnew1);
#pragma unroll
        for (int nt = 0; nt < 4; nt++) {
            sfr[nt][0] *= pf0; sfr[nt][1] *= pf0;
            sfr[nt][2] *= pf1; sfr[nt][3] *= pf1;
        }
#pragma unroll
        for (int n8 = 0; n8 < 8; n8++) {
            o_acc[n8][0] *= corr0; o_acc[n8][1] *= corr0;
            o_acc[n8][2] *= corr1; o_acc[n8][3] *= corr1;
        }

        // P -> A fragments (bf16 hi/lo) in registers
        unsigned pa_h[2][4], pa_l[2][4];
#pragma unroll
        for (int ks2 = 0; ks2 < 2; ks2++) {
            const int ntA = 2 * ks2, ntB = 2 * ks2 + 1;
            const float p00 = sfr[ntA][0], p01 = sfr[ntA][1];
            const float p02 = sfr[ntA][2], p03 = sfr[ntA][3];
            const float p10 = sfr[ntB][0], p11 = sfr[ntB][1];
            const float p12 = sfr[ntB][2], p13 = sfr[ntB][3];
            const bf16 h00 = __float2bfloat16_rn(p00), h01 = __float2bfloat16_rn(p01);
            const bf16 h02 = __float2bfloat16_rn(p02), h03 = __float2bfloat16_rn(p03);
            const bf16 h10 = __float2bfloat16_rn(p10), h11 = __float2bfloat16_rn(p11);
            const bf16 h12 = __float2bfloat16_rn(p12), h13 = __float2bfloat16_rn(p13);
            pa_h[ks2][0] = pack_bf16(h00, h01);
            pa_h[ks2][1] = pack_bf16(h02, h03);
            pa_h[ks2][2] = pack_bf16(h10, h11);
            pa_h[ks2][3] = pack_bf16(h12, h13);
            pa_l[ks2][0] = pack_bf16(
                __float2bfloat16_rn(p00 - __bfloat162float(h00)),
                __float2bfloat16_rn(p01 - __bfloat162float(h01)));
            pa_l[ks2][1] = pack_bf16(
                __float2bfloat16_rn(p02 - __bfloat162float(h02)),
                __float2bfloat16_rn(p03 - __bfloat162float(h03)));
            pa_l[ks2][2] = pack_bf16(
                __float2bfloat16_rn(p10 - __bfloat162float(h10)),
                __float2bfloat16_rn(p11 - __bfloat162float(h11)));
            pa_l[ks2][3] = pack_bf16(
                __float2bfloat16_rn(p12 - __bfloat162float(h12)),
                __float2bfloat16_rn(p13 - __bfloat162float(h13)));
        }

        // O += P V (this warp's k-half)
#pragma unroll
        for (int ks2 = 0; ks2 < 2; ks2++) {
#pragma unroll
            for (int nc = 0; nc < 4; nc++) {
                const unsigned offv =
                    ((wn * 32 + ks2 * 16 + vkr) * AST + nc * 16 + vnc) * 2;
                unsigned rh[4], rl[4];
                ldsm4t(rh, uVh + offv);
                ldsm4t(rl, uVl + offv);
                unsigned bh0[2] = {rh[0], rh[2]}, bh1[2] = {rh[1], rh[3]};
                unsigned bl0[2] = {rl[0], rl[2]}, bl1[2] = {rl[1], rl[3]};
                mma16816(o_acc[nc*2],   pa_h[ks2], bh0);
                mma16816(o_acc[nc*2],   pa_h[ks2], bl0);
                mma16816(o_acc[nc*2],   pa_l[ks2], bh0);
                mma16816(o_acc[nc*2+1], pa_h[ks2], bh1);
                mma16816(o_acc[nc*2+1], pa_h[ks2], bl1);
                mma16816(o_acc[nc*2+1], pa_l[ks2], bh1);
            }
        }
        // no bottom sync: next-iteration top sync orders buffer reuse
    }
    __syncthreads();   // all PV MMAs done before staging area reuse

    // cross-warp O reduction + split output
    float* red = (float*)(sm + AOFF_STAGE);     // [64][66]
    if (wn == 1) {
#pragma unroll
        for (int n8 = 0; n8 < 8; n8++) {
            const int col = n8 * 8 + 2 * t;
            red[(wm * 16 + g)     * 66 + col]     = o_acc[n8][0];
            red[(wm * 16 + g)     * 66 + col + 1] = o_acc[n8][1];
            red[(wm * 16 + g + 8) * 66 + col]     = o_acc[n8][2];
            red[(wm * 16 + g + 8) * 66 + col + 1] = o_acc[n8][3];
        }
    }
    __syncthreads();
    if (wn == 0) {
        const float inv0 = 1.f / l0r, inv1 = 1.f / l1r;
        const size_t obase = ((size_t)(b * SEQ + qb * 64)) * HIDN + h * HD;
#pragma unroll
        for (int n8 = 0; n8 < 8; n8++) {
            const int col = n8 * 8 + 2 * t;
            const float v0 = (o_acc[n8][0] + red[(wm*16+g)*66 + col])     * inv0;
            const float v1 = (o_acc[n8][1] + red[(wm*16+g)*66 + col + 1]) * inv0;
            const float v2 = (o_acc[n8][2] + red[(wm*16+g+8)*66 + col])     * inv1;
            const float v3 = (o_acc[n8][3] + red[(wm*16+g+8)*66 + col + 1]) * inv1;
            const bf16 h0 = __float2bfloat16_rn(v0), h1 = __float2bfloat16_rn(v1);
            const bf16 h2 = __float2bfloat16_rn(v2), h3 = __float2bfloat16_rn(v3);
            const size_t i0 = obase + (size_t)(wm * 16 + g) * HIDN + col;
            const size_t i1 = obase + (size_t)(wm * 16 + g + 8) * HIDN + col;
            *(unsigned*)(goh + i0) = pack_bf16(h0, h1);
            *(unsigned*)(gol + i0) = pack_bf16(
                __float2bfloat16_rn(v0 - __bfloat162float(h0)),
                __float2bfloat16_rn(v1 - __bfloat162float(h1)));
            *(unsigned*)(goh + i1) = pack_bf16(h2, h3);
            *(unsigned*)(gol + i1) = pack_bf16(
                __float2bfloat16_rn(v2 - __bfloat162float(h2)),
                __float2bfloat16_rn(v3 - __bfloat162float(h3)));
        }
    }
}

// ---------------------------------------------------------------------------
extern "C" void kernel_launch(void* const* d_in, const int* in_sizes, int n_in,
                              void* d_out, int out_size)
{
    const float* x  = (const float*)d_in[0];
    const float* Wq = (const float*)d_in[1];
    const float* bq = (const float*)d_in[2];
    const float* Wk = (const float*)d_in[3];
    const float* bk = (const float*)d_in[4];
    const float* Wv = (const float*)d_in[5];
    const float* bv = (const float*)d_in[6];
    const float* Wo = (const float*)d_in[7];
    const float* bo = (const float*)d_in[8];
    float* out = (float*)d_out;

    bf16 *xh, *xl, *w8, *qh, *ql, *kh, *kl, *vh, *vl, *ah, *al;
    cudaGetSymbolAddress((void**)&xh, g_xh);
    cudaGetSymbolAddress((void**)&xl, g_xl);
    cudaGetSymbolAddress((void**)&w8, g_w8);
    cudaGetSymbolAddress((void**)&qh, g_qh);
    cudaGetSymbolAddress((void**)&ql, g_ql);
    cudaGetSymbolAddress((void**)&kh, g_kh);
    cudaGetSymbolAddress((void**)&kl, g_kl);
    cudaGetSymbolAddress((void**)&vh, g_vh);
    cudaGetSymbolAddress((void**)&vl, g_vl);
    cudaGetSymbolAddress((void**)&ah, g_ah);
    cudaGetSymbolAddress((void**)&al, g_al);

    cudaFuncSetAttribute(gemm_mma3,
                         cudaFuncAttributeMaxDynamicSharedMemorySize, GSM_BYTES);
    cudaFuncSetAttribute(attn_mma2,
                         cudaFuncAttributeMaxDynamicSharedMemorySize, ATTN_SMEM);

    const int W2 = HIDN * HIDN;

    split_kernel<<<(MROWS*HIDN/8 + 255)/256, 256>>>(x, xh, xl, MROWS*HIDN/4);
    split_kernel<<<(W2/8 + 255)/256, 256>>>(Wq, w8 + 0*W2, w8 + 1*W2, W2/4);
    split_kernel<<<(W2/8 + 255)/256, 256>>>(Wk, w8 + 2*W2, w8 + 3*W2, W2/4);
    split_kernel<<<(W2/8 + 255)/256, 256>>>(Wv, w8 + 4*W2, w8 + 5*W2, W2/4);
    split_kernel<<<(W2/8 + 255)/256, 256>>>(Wo, w8 + 6*W2, w8 + 7*W2, W2/4);

    dim3 ggrid(HIDN / 128, MROWS / 128);

    gemm_mma3<<<ggrid, 256, GSM_BYTES>>>(xh, xl, w8 + 0*W2, w8 + 1*W2, bq,
                                         nullptr, qh, ql, 0.125f, 1);
    gemm_mma3<<<ggrid, 256, GSM_BYTES>>>(xh, xl, w8 + 2*W2, w8 + 3*W2, bk,
                                         nullptr, kh, kl, 1.0f, 1);
    gemm_mma3<<<ggrid, 256, GSM_BYTES>>>(xh, xl, w8 + 4*W2, w8 + 5*W2, bv,
                                         nullptr, vh, vl, 1.0f, 1);

    attn_mma2<<<dim3(NQB, HEADS, BSZ), 256, ATTN_SMEM>>>(qh, ql, kh, kl,
                                                         vh, vl, ah, al);

    gemm_mma3<<<ggrid, 256, GSM_BYTES>>>(ah, al, w8 + 6*W2, w8 + 7*W2, bo,
                                         out, nullptr, nullptr, 1.0f, 0);
}